// round 3
// baseline (speedup 1.0000x reference)
#include <cuda_runtime.h>
#include <math.h>

#define BATCH 4
#define SEQ   2048
#define EMB   1024
#define NH    16
#define HS    64
#define DFF   4096
#define MROWS (BATCH*SEQ)   // 8192

// ---------------- scratch (device globals; no allocation) ----------------
__device__ float g_h [MROWS*EMB];   // LN out, then attn out (reused)
__device__ float g_q [MROWS*EMB];
__device__ float g_k [MROWS*EMB];
__device__ float g_v [MROWS*EMB];
__device__ float g_x1[MROWS*EMB];   // post-attention residual stream
__device__ float g_ff[MROWS*DFF];
__device__ int   g_len[BATCH];

// ---------------- lengths from key_padding_mask (dtype-robust) ----------------
__global__ void lengths_kernel(const unsigned char* mraw) {
    __shared__ int s_cnt[BATCH];
    __shared__ int s_isbool;
    int tid = threadIdx.x;
    if (tid < BATCH) s_cnt[tid] = 0;
    if (tid == 0) {
        // bool layout: bytes 1..3 are mask[0][1..3] == 1 (length >= 1024)
        // int32 layout: bytes 1..3 are high bytes of value 1 -> 0
        s_isbool = (mraw[1] | mraw[2] | mraw[3]) ? 1 : 0;
    }
    __syncthreads();
    for (int b = 0; b < BATCH; b++) {
        int c = 0;
        if (s_isbool) {
            const unsigned char* p = mraw + (size_t)b * SEQ;
            for (int t = tid; t < SEQ; t += blockDim.x) c += p[t] ? 1 : 0;
        } else {
            const int* p = (const int*)mraw + (size_t)b * SEQ;
            for (int t = tid; t < SEQ; t += blockDim.x) c += p[t] ? 1 : 0;
        }
        atomicAdd(&s_cnt[b], c);
    }
    __syncthreads();
    if (tid < BATCH) g_len[tid] = s_cnt[tid];
}

// ---------------- LayerNorm (+ mask on output) ----------------
__global__ void __launch_bounds__(256) ln_kernel(
    const float* __restrict__ x, const float* __restrict__ w,
    const float* __restrict__ bia, float* __restrict__ y)
{
    int row = blockIdx.x;
    int b = row >> 11, t = row & (SEQ - 1);
    const float* xr = x + (size_t)row * EMB;
    float s = 0.f, sq = 0.f;
    for (int i = threadIdx.x; i < EMB; i += 256) {
        float v = xr[i]; s += v; sq += v * v;
    }
    #pragma unroll
    for (int o = 16; o; o >>= 1) {
        s  += __shfl_xor_sync(~0u, s,  o);
        sq += __shfl_xor_sync(~0u, sq, o);
    }
    __shared__ float red[16];
    __shared__ float s_mu, s_rstd;
    int wid = threadIdx.x >> 5, lid = threadIdx.x & 31;
    if (lid == 0) { red[wid] = s; red[8 + wid] = sq; }
    __syncthreads();
    if (threadIdx.x == 0) {
        float S = 0.f, SQ = 0.f;
        for (int i = 0; i < 8; i++) { S += red[i]; SQ += red[8 + i]; }
        float mu = S * (1.f / EMB);
        float var = SQ * (1.f / EMB) - mu * mu;
        s_mu = mu; s_rstd = rsqrtf(var + 1e-5f);
    }
    __syncthreads();
    float mk = (t < g_len[b]) ? 1.f : 0.f;
    float mu = s_mu, rstd = s_rstd;
    float* yr = y + (size_t)row * EMB;
    for (int i = threadIdx.x; i < EMB; i += 256)
        yr[i] = ((xr[i] - mu) * rstd * w[i] + bia[i]) * mk;
}

// ---------------- SGEMM 128x128x8, 256 threads, 8x8/thread ----------------
// C[M,N] = A[M,K] @ B[K,N] (+Bias[N]) (+Res[M,N]) (relu?) (*rowmask?)
__global__ void __launch_bounds__(256) gemm_kernel(
    const float* __restrict__ A, const float* __restrict__ B,
    const float* __restrict__ Res, const float* __restrict__ Bias,
    float* __restrict__ C, int M, int N, int K, int doRelu, int doMask)
{
    __shared__ float As[8][132];
    __shared__ float Bs[8][132];
    int tid = threadIdx.x;
    int tx = tid & 15, ty = tid >> 4;
    int m0 = blockIdx.y * 128, n0 = blockIdx.x * 128;
    int arow = tid >> 1, ak = (tid & 1) * 4;
    int brow = tid >> 5, bcol = (tid & 31) * 4;
    const float* Ap = A + (size_t)(m0 + arow) * K + ak;
    const float* Bp = B + (size_t)brow * N + n0 + bcol;
    float acc[8][8] = {};
    for (int k0 = 0; k0 < K; k0 += 8) {
        float4 av = *(const float4*)Ap;
        float4 bv = *(const float4*)Bp;
        As[ak + 0][arow] = av.x; As[ak + 1][arow] = av.y;
        As[ak + 2][arow] = av.z; As[ak + 3][arow] = av.w;
        *(float4*)&Bs[brow][bcol] = bv;
        __syncthreads();
        #pragma unroll
        for (int kk = 0; kk < 8; kk++) {
            float a[8], b[8];
            *(float4*)(a)     = *(const float4*)&As[kk][ty * 4];
            *(float4*)(a + 4) = *(const float4*)&As[kk][64 + ty * 4];
            *(float4*)(b)     = *(const float4*)&Bs[kk][tx * 4];
            *(float4*)(b + 4) = *(const float4*)&Bs[kk][64 + tx * 4];
            #pragma unroll
            for (int i = 0; i < 8; i++)
                #pragma unroll
                for (int j = 0; j < 8; j++)
                    acc[i][j] = fmaf(a[i], b[j], acc[i][j]);
        }
        __syncthreads();
        Ap += 8;
        Bp += (size_t)8 * N;
    }
    #pragma unroll
    for (int i = 0; i < 8; i++) {
        int m = m0 + ((i < 4) ? (ty * 4 + i) : (60 + ty * 4 + i));
        float mk = 1.f;
        if (doMask) { int bb = m >> 11, t = m & (SEQ - 1); mk = (t < g_len[bb]) ? 1.f : 0.f; }
        #pragma unroll
        for (int j = 0; j < 8; j++) {
            int n = n0 + ((j < 4) ? (tx * 4 + j) : (60 + tx * 4 + j));
            float v = acc[i][j];
            if (Bias)   v += Bias[n];
            if (Res)    v += Res[(size_t)m * N + n];
            if (doRelu) v = fmaxf(v, 0.f);
            v *= mk;
            C[(size_t)m * N + n] = v;
        }
    }
}

// ---------------- Flash attention, 64q x 64k tiles, online softmax ----------------
#define PADW 68
#define ATTN_SMEM ((4 * 64 * PADW + 3 * 64) * 4)

__global__ void __launch_bounds__(256) attn_kernel(
    const float* __restrict__ Q, const float* __restrict__ Kb,
    const float* __restrict__ Vb, float* __restrict__ O)
{
    extern __shared__ float sm[];
    float* Qs = sm;                // [64][PADW], row-major (r, d)
    float* Kt = Qs + 64 * PADW;    // [64][PADW], transposed (d, c)
    float* Vs = Kt + 64 * PADW;    // [64][PADW], row-major (k, d)
    float* Ss = Vs + 64 * PADW;    // [64][PADW], scores/probs (r, c)
    float* s_m = Ss + 64 * PADW;   // [64]
    float* s_l = s_m + 64;         // [64]
    float* s_c = s_l + 64;         // [64]

    int tid = threadIdx.x, tx = tid & 15, ty = tid >> 4;
    int b = blockIdx.z, h = blockIdx.y, q0 = blockIdx.x * 64;
    int len = g_len[b];
    size_t base = ((size_t)b * SEQ) * EMB + (size_t)h * HS;

    #pragma unroll
    for (int i = 0; i < 16; i++) {
        int idx = tid + i * 256, r = idx >> 6, d = idx & 63;
        Qs[r * PADW + d] = Q[base + (size_t)(q0 + r) * EMB + d];
    }
    if (tid < 64) { s_m[tid] = -1e30f; s_l[tid] = 0.f; }

    float Oacc[4][4] = {};
    const float scale = 0.03125f; // 1024^-0.5
    int nT = blockIdx.x + 1;

    for (int kt = 0; kt < nT; kt++) {
        int s0 = kt * 64;
        __syncthreads();  // protect smem tiles (also covers Qs/s_m init on kt=0)
        #pragma unroll
        for (int i = 0; i < 16; i++) {
            int idx = tid + i * 256, r = idx >> 6, d = idx & 63;
            size_t g = base + (size_t)(s0 + r) * EMB + d;
            Kt[d * PADW + r] = Kb[g];
            Vs[r * PADW + d] = Vb[g];
        }
        __syncthreads();

        // S = Q K^T
        float S[4][4] = {};
        #pragma unroll 8
        for (int kk = 0; kk < 64; kk++) {
            float a[4], bb[4];
            a[0] = Qs[(4 * ty + 0) * PADW + kk];
            a[1] = Qs[(4 * ty + 1) * PADW + kk];
            a[2] = Qs[(4 * ty + 2) * PADW + kk];
            a[3] = Qs[(4 * ty + 3) * PADW + kk];
            *(float4*)bb = *(const float4*)&Kt[kk * PADW + 4 * tx];
            #pragma unroll
            for (int i = 0; i < 4; i++)
                #pragma unroll
                for (int j = 0; j < 4; j++)
                    S[i][j] = fmaf(a[i], bb[j], S[i][j]);
        }
        // scale + causal + padding mask -> Ss
        #pragma unroll
        for (int i = 0; i < 4; i++) {
            int qi = q0 + 4 * ty + i;
            #pragma unroll
            for (int j = 0; j < 4; j++) {
                int kj = s0 + 4 * tx + j;
                float v = S[i][j] * scale;
                if (kj > qi || kj >= len) v = -1e30f;
                Ss[(4 * ty + i) * PADW + 4 * tx + j] = v;
            }
        }
        __syncthreads();

        // online softmax bookkeeping: 4 threads per row
        {
            int r = tid >> 2, g = tid & 3;
            float* srow = &Ss[r * PADW + g * 16];
            float tmax = -1e30f;
            #pragma unroll
            for (int c = 0; c < 16; c++) tmax = fmaxf(tmax, srow[c]);
            tmax = fmaxf(tmax, __shfl_xor_sync(~0u, tmax, 1));
            tmax = fmaxf(tmax, __shfl_xor_sync(~0u, tmax, 2));
            float mOld = s_m[r];
            float mNew = fmaxf(mOld, tmax);
            float tsum = 0.f;
            #pragma unroll
            for (int c = 0; c < 16; c++) {
                float p = __expf(srow[c] - mNew);
                srow[c] = p; tsum += p;
            }
            tsum += __shfl_xor_sync(~0u, tsum, 1);
            tsum += __shfl_xor_sync(~0u, tsum, 2);
            if (g == 0) {
                float corr = __expf(mOld - mNew);
                s_c[r] = corr;
                s_l[r] = s_l[r] * corr + tsum;
                s_m[r] = mNew;
            }
        }
        __syncthreads();

        // O = O * corr + P @ V
        #pragma unroll
        for (int i = 0; i < 4; i++) {
            float cf = s_c[4 * ty + i];
            #pragma unroll
            for (int j = 0; j < 4; j++) Oacc[i][j] *= cf;
        }
        #pragma unroll 8
        for (int kk = 0; kk < 64; kk++) {
            float p[4], vv[4];
            p[0] = Ss[(4 * ty + 0) * PADW + kk];
            p[1] = Ss[(4 * ty + 1) * PADW + kk];
            p[2] = Ss[(4 * ty + 2) * PADW + kk];
            p[3] = Ss[(4 * ty + 3) * PADW + kk];
            *(float4*)vv = *(const float4*)&Vs[kk * PADW + 4 * tx];
            #pragma unroll
            for (int i = 0; i < 4; i++)
                #pragma unroll
                for (int j = 0; j < 4; j++)
                    Oacc[i][j] = fmaf(p[i], vv[j], Oacc[i][j]);
        }
    }

    #pragma unroll
    for (int i = 0; i < 4; i++) {
        float inv = 1.f / s_l[4 * ty + i];
        float4 o;
        o.x = Oacc[i][0] * inv; o.y = Oacc[i][1] * inv;
        o.z = Oacc[i][2] * inv; o.w = Oacc[i][3] * inv;
        *(float4*)&O[base + (size_t)(q0 + 4 * ty + i) * EMB + 4 * tx] = o;
    }
}

// ---------------- launch ----------------
extern "C" void kernel_launch(void* const* d_in, const int* in_sizes, int n_in,
                              void* d_out, int out_size)
{
    const float* x      = (const float*)d_in[0];
    const unsigned char* mask = (const unsigned char*)d_in[1];
    const float* wq     = (const float*)d_in[2];
    const float* wk     = (const float*)d_in[3];
    const float* wv     = (const float*)d_in[4];
    const float* proj_w = (const float*)d_in[5];
    const float* proj_b = (const float*)d_in[6];
    const float* ff_w1  = (const float*)d_in[7];
    const float* ff_b1  = (const float*)d_in[8];
    const float* ff_w2  = (const float*)d_in[9];
    const float* ff_b2  = (const float*)d_in[10];
    const float* ln1w   = (const float*)d_in[11];
    const float* ln1b   = (const float*)d_in[12];
    const float* ln2w   = (const float*)d_in[13];
    const float* ln2b   = (const float*)d_in[14];
    float* out = (float*)d_out;

    float *h, *q, *k, *v, *x1, *ff;
    cudaGetSymbolAddress((void**)&h,  g_h);
    cudaGetSymbolAddress((void**)&q,  g_q);
    cudaGetSymbolAddress((void**)&k,  g_k);
    cudaGetSymbolAddress((void**)&v,  g_v);
    cudaGetSymbolAddress((void**)&x1, g_x1);
    cudaGetSymbolAddress((void**)&ff, g_ff);

    cudaFuncSetAttribute(attn_kernel,
        cudaFuncAttributeMaxDynamicSharedMemorySize, ATTN_SMEM);

    lengths_kernel<<<1, 256>>>(mask);

    // h = LN1(x) * m
    ln_kernel<<<MROWS, 256>>>(x, ln1w, ln1b, h);

    // q,k,v = h @ w{q,k,v}
    dim3 gsm(EMB / 128, MROWS / 128);
    gemm_kernel<<<gsm, 256>>>(h, wq, nullptr, nullptr, q, MROWS, EMB, EMB, 0, 0);
    gemm_kernel<<<gsm, 256>>>(h, wk, nullptr, nullptr, k, MROWS, EMB, EMB, 0, 0);
    gemm_kernel<<<gsm, 256>>>(h, wv, nullptr, nullptr, v, MROWS, EMB, EMB, 0, 0);

    // attn out -> h (reuse)
    attn_kernel<<<dim3(SEQ / 64, NH, BATCH), 256, ATTN_SMEM>>>(q, k, v, h);

    // x1 = x + h @ proj_w + proj_b
    gemm_kernel<<<gsm, 256>>>(h, proj_w, x, proj_b, x1, MROWS, EMB, EMB, 0, 0);

    // h = LN2(x1) * m
    ln_kernel<<<MROWS, 256>>>(x1, ln2w, ln2b, h);

    // ff = relu(h @ ff_w1 + b1)
    gemm_kernel<<<dim3(DFF / 128, MROWS / 128), 256>>>(
        h, ff_w1, nullptr, ff_b1, ff, MROWS, DFF, EMB, 1, 0);

    // out = (x1 + ff @ ff_w2 + b2) * m
    gemm_kernel<<<gsm, 256>>>(ff, ff_w2, x1, ff_b2, out, MROWS, EMB, DFF, 0, 1);
}

// round 5
// speedup vs baseline: 1.4501x; 1.4501x over previous
#include <cuda_runtime.h>
#include <cuda_bf16.h>
#include <math.h>
#include <stdint.h>

#define BATCH 4
#define SEQ   2048
#define EMB   1024
#define NH    16
#define HS    64
#define DFF   4096
#define MROWS (BATCH*SEQ)   // 8192
#define QKVW  (3*EMB)       // 3072

// ---------------- scratch (device globals; no allocation) ----------------
__device__ __align__(256) __nv_bfloat16 g_ahi [MROWS*EMB];
__device__ __align__(256) __nv_bfloat16 g_alo [MROWS*EMB];
__device__ __align__(256) __nv_bfloat16 g_ffhi[MROWS*DFF];
__device__ __align__(256) __nv_bfloat16 g_fflo[MROWS*DFF];
__device__ __align__(256) __nv_bfloat16 g_wqkvh[QKVW*EMB];
__device__ __align__(256) __nv_bfloat16 g_wqkvl[QKVW*EMB];
__device__ __align__(256) __nv_bfloat16 g_wprojh[EMB*EMB];
__device__ __align__(256) __nv_bfloat16 g_wprojl[EMB*EMB];
__device__ __align__(256) __nv_bfloat16 g_wff1h[DFF*EMB];
__device__ __align__(256) __nv_bfloat16 g_wff1l[DFF*EMB];
__device__ __align__(256) __nv_bfloat16 g_wff2h[EMB*DFF];
__device__ __align__(256) __nv_bfloat16 g_wff2l[EMB*DFF];
__device__ __align__(256) float g_qkv[MROWS*QKVW];
__device__ __align__(256) float g_x1 [MROWS*EMB];
__device__ int g_len[BATCH];

// ---------------- helpers ----------------
__device__ __forceinline__ uint32_t smem_u32(const void* p) {
    uint32_t a;
    asm("{ .reg .u64 t; cvta.to.shared.u64 t, %1; cvt.u32.u64 %0, t; }" : "=r"(a) : "l"(p));
    return a;
}
__device__ __forceinline__ void cp_async16(uint32_t dst, const void* src) {
    asm volatile("cp.async.cg.shared.global [%0], [%1], 16;\n" :: "r"(dst), "l"(src));
}
#define CP_COMMIT() asm volatile("cp.async.commit_group;\n" ::: "memory")
#define CP_WAIT0()  asm volatile("cp.async.wait_group 0;\n" ::: "memory")

__device__ __forceinline__ void ldsm4(uint32_t* r, uint32_t addr) {
    asm volatile("ldmatrix.sync.aligned.m8n8.x4.shared.b16 {%0,%1,%2,%3}, [%4];"
        : "=r"(r[0]), "=r"(r[1]), "=r"(r[2]), "=r"(r[3]) : "r"(addr));
}
__device__ __forceinline__ void mma_bf16(float* d, const uint32_t* a, const uint32_t* b) {
    asm volatile("mma.sync.aligned.m16n8k16.row.col.f32.bf16.bf16.f32 "
        "{%0,%1,%2,%3}, {%4,%5,%6,%7}, {%8,%9}, {%0,%1,%2,%3};"
        : "+f"(d[0]), "+f"(d[1]), "+f"(d[2]), "+f"(d[3])
        : "r"(a[0]), "r"(a[1]), "r"(a[2]), "r"(a[3]), "r"(b[0]), "r"(b[1]));
}
__device__ __forceinline__ uint32_t sw128(uint32_t off) {
    return off ^ ((off >> 3) & 0x70);
}
__device__ __forceinline__ void split_bf16(float v, __nv_bfloat16& h, __nv_bfloat16& l) {
    h = __float2bfloat16(v);
    l = __float2bfloat16(v - __bfloat162float(h));
}

// ---------------- lengths from key_padding_mask (dtype-robust) ----------------
__global__ void lengths_kernel(const unsigned char* mraw) {
    __shared__ int s_cnt[BATCH];
    __shared__ int s_isbool;
    int tid = threadIdx.x;
    if (tid < BATCH) s_cnt[tid] = 0;
    if (tid == 0) s_isbool = (mraw[1] | mraw[2] | mraw[3]) ? 1 : 0;
    __syncthreads();
    for (int b = 0; b < BATCH; b++) {
        int c = 0;
        if (s_isbool) {
            const unsigned char* p = mraw + (size_t)b * SEQ;
            for (int t = tid; t < SEQ; t += blockDim.x) c += p[t] ? 1 : 0;
        } else {
            const int* p = (const int*)mraw + (size_t)b * SEQ;
            for (int t = tid; t < SEQ; t += blockDim.x) c += p[t] ? 1 : 0;
        }
        atomicAdd(&s_cnt[b], c);
    }
    __syncthreads();
    if (tid < BATCH) g_len[tid] = s_cnt[tid];
}

// ---------------- weight transpose + hi/lo split: W[K,N] -> T[N,K] bf16 x2 ----------------
__global__ void __launch_bounds__(256) wsplit_kernel(
    const float* __restrict__ W, __nv_bfloat16* __restrict__ Th,
    __nv_bfloat16* __restrict__ Tl, int K, int N, int rowOff, int ldt)
{
    __shared__ float t[32][33];
    int n0 = blockIdx.x * 32, k0 = blockIdx.y * 32;
    int tx = threadIdx.x & 31, ty = threadIdx.x >> 5;
    #pragma unroll
    for (int i = 0; i < 32; i += 8)
        t[ty + i][tx] = W[(size_t)(k0 + ty + i) * N + n0 + tx];
    __syncthreads();
    #pragma unroll
    for (int i = 0; i < 32; i += 8) {
        float v = t[tx][ty + i];
        size_t o = (size_t)(rowOff + n0 + ty + i) * ldt + k0 + tx;
        __nv_bfloat16 h, l; split_bf16(v, h, l);
        Th[o] = h; Tl[o] = l;
    }
}

// ---------------- LayerNorm -> masked, bf16 hi/lo split output ----------------
__global__ void __launch_bounds__(256) ln_split_kernel(
    const float* __restrict__ x, const float* __restrict__ w,
    const float* __restrict__ bia, __nv_bfloat16* __restrict__ yh,
    __nv_bfloat16* __restrict__ yl)
{
    int row = blockIdx.x;
    int b = row >> 11, t = row & (SEQ - 1);
    const float* xr = x + (size_t)row * EMB;
    float s = 0.f, sq = 0.f;
    for (int i = threadIdx.x; i < EMB; i += 256) { float v = xr[i]; s += v; sq += v * v; }
    #pragma unroll
    for (int o = 16; o; o >>= 1) {
        s  += __shfl_xor_sync(~0u, s,  o);
        sq += __shfl_xor_sync(~0u, sq, o);
    }
    __shared__ float red[16];
    __shared__ float s_mu, s_rstd;
    int wid = threadIdx.x >> 5, lid = threadIdx.x & 31;
    if (lid == 0) { red[wid] = s; red[8 + wid] = sq; }
    __syncthreads();
    if (threadIdx.x == 0) {
        float S = 0.f, SQ = 0.f;
        for (int i = 0; i < 8; i++) { S += red[i]; SQ += red[8 + i]; }
        float mu = S * (1.f / EMB);
        float var = SQ * (1.f / EMB) - mu * mu;
        s_mu = mu; s_rstd = rsqrtf(var + 1e-5f);
    }
    __syncthreads();
    float mk = (t < g_len[b]) ? 1.f : 0.f;
    float mu = s_mu, rstd = s_rstd;
    for (int i = threadIdx.x; i < EMB; i += 256) {
        float v = ((xr[i] - mu) * rstd * w[i] + bia[i]) * mk;
        __nv_bfloat16 h, l; split_bf16(v, h, l);
        yh[(size_t)row * EMB + i] = h;
        yl[(size_t)row * EMB + i] = l;
    }
}

// ---------------- mma.sync GEMM: C[M,N] = A @ B^T  (split-bf16, fp32 acc) ----------------
// A: Ahi/Alo [M,K]; B: Bhi/Blo [N,K]. 128x128 tile, 8 warps (2x4), warp 64x32.
// Epilogue: +Bias[N], +Res, relu, rowmask; out f32 Cf OR bf16 Chi/Clo.
#define GEMM_SMEM (2 * 65536)

__global__ void __launch_bounds__(256) gemm_mma(
    const __nv_bfloat16* __restrict__ Ahi, const __nv_bfloat16* __restrict__ Alo,
    const __nv_bfloat16* __restrict__ Bhi, const __nv_bfloat16* __restrict__ Blo,
    const float* __restrict__ Res, const float* __restrict__ Bias,
    float* __restrict__ Cf, __nv_bfloat16* __restrict__ Chi, __nv_bfloat16* __restrict__ Clo,
    int K, int ldc, int doRelu, int doMask)
{
    extern __shared__ char smem[];
    uint32_t sb = smem_u32(smem);
    int tid = threadIdx.x;
    int lane = tid & 31, wid = tid >> 5;
    int wm = (wid >> 2) * 64;     // warp row offset
    int wn = (wid & 3) * 32;      // warp col offset
    int m0 = blockIdx.y * 128, n0 = blockIdx.x * 128;

    int nc = K >> 6;

    // chunk loader: 4 tiles (Ahi,Alo,Bhi,Blo) 128 rows x 128B, SW128
    auto load_chunk = [&](uint32_t st, int kc) {
        #pragma unroll
        for (int i = 0; i < 4; i++) {
            int g = tid + i * 256;          // 0..1023
            int r = g >> 3, c16 = g & 7;
            uint32_t sw = sw128(r * 128 + c16 * 16);
            size_t ao = (size_t)(m0 + r) * K + kc + c16 * 8;
            size_t bo = (size_t)(n0 + r) * K + kc + c16 * 8;
            cp_async16(st + 0 * 16384 + sw, Ahi + ao);
            cp_async16(st + 1 * 16384 + sw, Alo + ao);
            cp_async16(st + 2 * 16384 + sw, Bhi + bo);
            cp_async16(st + 3 * 16384 + sw, Blo + bo);
        }
        CP_COMMIT();
    };

    // ldmatrix lane-role constants
    int grp = lane >> 3, lrow = lane & 7;
    // A: matrices {rows+0-7,k0},{rows+8-15,k0},{rows+0-7,k1},{rows+8-15,k1}
    int a_r = lrow + ((grp & 1) ? 8 : 0);
    int a_c = grp >> 1;
    // B: matrices {n+0-7,k0},{n+0-7,k1},{n+8-15,k0},{n+8-15,k1}
    int b_r = lrow + ((grp >> 1) ? 8 : 0);
    int b_c = grp & 1;

    float d[4][4][4];
    #pragma unroll
    for (int i = 0; i < 4; i++)
        #pragma unroll
        for (int j = 0; j < 4; j++)
            #pragma unroll
            for (int q = 0; q < 4; q++) d[i][j][q] = 0.f;

    load_chunk(sb, 0);
    CP_WAIT0();
    __syncthreads();

    for (int c = 0; c < nc; c++) {
        uint32_t st = sb + (c & 1) * 65536;
        if (c + 1 < nc) load_chunk(sb + ((c + 1) & 1) * 65536, (c + 1) * 64);

        #pragma unroll
        for (int ks = 0; ks < 4; ks++) {
            uint32_t ah[4][4], al[4][4], bh[4][2], bl[4][2];
            #pragma unroll
            for (int mt = 0; mt < 4; mt++) {
                uint32_t off = sw128((wm + mt * 16 + a_r) * 128 + (2 * ks + a_c) * 16);
                ldsm4(ah[mt], st + off);
                ldsm4(al[mt], st + 16384 + off);
            }
            #pragma unroll
            for (int np = 0; np < 2; np++) {
                uint32_t off = sw128((wn + np * 16 + b_r) * 128 + (2 * ks + b_c) * 16);
                uint32_t th[4], tl[4];
                ldsm4(th, st + 32768 + off);
                ldsm4(tl, st + 49152 + off);
                bh[np * 2][0] = th[0]; bh[np * 2][1] = th[1];
                bh[np * 2 + 1][0] = th[2]; bh[np * 2 + 1][1] = th[3];
                bl[np * 2][0] = tl[0]; bl[np * 2][1] = tl[1];
                bl[np * 2 + 1][0] = tl[2]; bl[np * 2 + 1][1] = tl[3];
            }
            #pragma unroll
            for (int mt = 0; mt < 4; mt++)
                #pragma unroll
                for (int nt = 0; nt < 4; nt++) {
                    mma_bf16(d[mt][nt], ah[mt], bh[nt]);
                    mma_bf16(d[mt][nt], ah[mt], bl[nt]);
                    mma_bf16(d[mt][nt], al[mt], bh[nt]);
                }
        }
        if (c + 1 < nc) CP_WAIT0();
        __syncthreads();
    }

    // ---- epilogue: stage f32 accum through smem (reuse stage memory) ----
    float* eb = (float*)smem;    // [128][132]
    int fr = lane >> 2, fc = (lane & 3) * 2;
    #pragma unroll
    for (int mt = 0; mt < 4; mt++)
        #pragma unroll
        for (int nt = 0; nt < 4; nt++) {
            int rr = wm + mt * 16 + fr;
            int cc = wn + nt * 8 + fc;
            *(float2*)&eb[rr * 132 + cc]       = make_float2(d[mt][nt][0], d[mt][nt][1]);
            *(float2*)&eb[(rr + 8) * 132 + cc] = make_float2(d[mt][nt][2], d[mt][nt][3]);
        }
    __syncthreads();

    #pragma unroll
    for (int it = 0; it < 16; it++) {
        int idx = tid + it * 256;          // 0..4095
        int rr = idx >> 5;
        int cc = (idx & 31) * 4;
        int m = m0 + rr, n = n0 + cc;
        float4 v = *(float4*)&eb[rr * 132 + cc];
        if (Bias) {
            v.x += Bias[n]; v.y += Bias[n + 1]; v.z += Bias[n + 2]; v.w += Bias[n + 3];
        }
        if (Res) {
            float4 rv = *(const float4*)&Res[(size_t)m * ldc + n];
            v.x += rv.x; v.y += rv.y; v.z += rv.z; v.w += rv.w;
        }
        if (doRelu) {
            v.x = fmaxf(v.x, 0.f); v.y = fmaxf(v.y, 0.f);
            v.z = fmaxf(v.z, 0.f); v.w = fmaxf(v.w, 0.f);
        }
        if (doMask) {
            int bb = m >> 11, t = m & (SEQ - 1);
            float mk = (t < g_len[bb]) ? 1.f : 0.f;
            v.x *= mk; v.y *= mk; v.z *= mk; v.w *= mk;
        }
        if (Chi) {
            __nv_bfloat16 h[4], l[4];
            split_bf16(v.x, h[0], l[0]); split_bf16(v.y, h[1], l[1]);
            split_bf16(v.z, h[2], l[2]); split_bf16(v.w, h[3], l[3]);
            *(uint2*)&Chi[(size_t)m * ldc + n] = *(uint2*)h;
            *(uint2*)&Clo[(size_t)m * ldc + n] = *(uint2*)l;
        } else {
            *(float4*)&Cf[(size_t)m * ldc + n] = v;
        }
    }
}

// ---------------- Flash attention (fp32), reads packed QKV, writes bf16 hi/lo ----------------
#define PADW 68
#define ATTN_SMEM ((4 * 64 * PADW + 3 * 64) * 4)

__global__ void __launch_bounds__(256) attn_kernel(
    const float* __restrict__ QKV, __nv_bfloat16* __restrict__ Oh,
    __nv_bfloat16* __restrict__ Ol)
{
    extern __shared__ float sm[];
    float* Qs = sm;
    float* Kt = Qs + 64 * PADW;
    float* Vs = Kt + 64 * PADW;
    float* Ss = Vs + 64 * PADW;
    float* s_m = Ss + 64 * PADW;
    float* s_l = s_m + 64;
    float* s_c = s_l + 64;

    int tid = threadIdx.x, tx = tid & 15, ty = tid >> 4;
    int b = blockIdx.z, h = blockIdx.y, q0 = blockIdx.x * 64;
    int len = g_len[b];
    size_t base = ((size_t)b * SEQ) * QKVW + (size_t)h * HS;

    #pragma unroll
    for (int i = 0; i < 16; i++) {
        int idx = tid + i * 256, r = idx >> 6, d = idx & 63;
        Qs[r * PADW + d] = QKV[base + (size_t)(q0 + r) * QKVW + d];
    }
    if (tid < 64) { s_m[tid] = -1e30f; s_l[tid] = 0.f; }

    float Oacc[4][4] = {};
    const float scale = 0.03125f;
    int nT = blockIdx.x + 1;

    for (int kt = 0; kt < nT; kt++) {
        int s0 = kt * 64;
        __syncthreads();
        #pragma unroll
        for (int i = 0; i < 16; i++) {
            int idx = tid + i * 256, r = idx >> 6, d = idx & 63;
            size_t g = base + (size_t)(s0 + r) * QKVW + d;
            Kt[d * PADW + r] = QKV[g + EMB];
            Vs[r * PADW + d] = QKV[g + 2 * EMB];
        }
        __syncthreads();

        float S[4][4] = {};
        #pragma unroll 8
        for (int kk = 0; kk < 64; kk++) {
            float a[4], bb[4];
            a[0] = Qs[(4 * ty + 0) * PADW + kk];
            a[1] = Qs[(4 * ty + 1) * PADW + kk];
            a[2] = Qs[(4 * ty + 2) * PADW + kk];
            a[3] = Qs[(4 * ty + 3) * PADW + kk];
            *(float4*)bb = *(const float4*)&Kt[kk * PADW + 4 * tx];
            #pragma unroll
            for (int i = 0; i < 4; i++)
                #pragma unroll
                for (int j = 0; j < 4; j++)
                    S[i][j] = fmaf(a[i], bb[j], S[i][j]);
        }
        #pragma unroll
        for (int i = 0; i < 4; i++) {
            int qi = q0 + 4 * ty + i;
            #pragma unroll
            for (int j = 0; j < 4; j++) {
                int kj = s0 + 4 * tx + j;
                float v = S[i][j] * scale;
                if (kj > qi || kj >= len) v = -1e30f;
                Ss[(4 * ty + i) * PADW + 4 * tx + j] = v;
            }
        }
        __syncthreads();
        {
            int r = tid >> 2, g = tid & 3;
            float* srow = &Ss[r * PADW + g * 16];
            float tmax = -1e30f;
            #pragma unroll
            for (int c = 0; c < 16; c++) tmax = fmaxf(tmax, srow[c]);
            tmax = fmaxf(tmax, __shfl_xor_sync(~0u, tmax, 1));
            tmax = fmaxf(tmax, __shfl_xor_sync(~0u, tmax, 2));
            float mOld = s_m[r];
            float mNew = fmaxf(mOld, tmax);
            float tsum = 0.f;
            #pragma unroll
            for (int c = 0; c < 16; c++) {
                float p = __expf(srow[c] - mNew);
                srow[c] = p; tsum += p;
            }
            tsum += __shfl_xor_sync(~0u, tsum, 1);
            tsum += __shfl_xor_sync(~0u, tsum, 2);
            if (g == 0) {
                float corr = __expf(mOld - mNew);
                s_c[r] = corr;
                s_l[r] = s_l[r] * corr + tsum;
                s_m[r] = mNew;
            }
        }
        __syncthreads();
        #pragma unroll
        for (int i = 0; i < 4; i++) {
            float cf = s_c[4 * ty + i];
            #pragma unroll
            for (int j = 0; j < 4; j++) Oacc[i][j] *= cf;
        }
        #pragma unroll 8
        for (int kk = 0; kk < 64; kk++) {
            float p[4], vv[4];
            p[0] = Ss[(4 * ty + 0) * PADW + kk];
            p[1] = Ss[(4 * ty + 1) * PADW + kk];
            p[2] = Ss[(4 * ty + 2) * PADW + kk];
            p[3] = Ss[(4 * ty + 3) * PADW + kk];
            *(float4*)vv = *(const float4*)&Vs[kk * PADW + 4 * tx];
            #pragma unroll
            for (int i = 0; i < 4; i++)
                #pragma unroll
                for (int j = 0; j < 4; j++)
                    Oacc[i][j] = fmaf(p[i], vv[j], Oacc[i][j]);
        }
    }

    size_t obase = ((size_t)b * SEQ) * EMB + (size_t)h * HS;
    #pragma unroll
    for (int i = 0; i < 4; i++) {
        float inv = 1.f / s_l[4 * ty + i];
        __nv_bfloat16 hh[4], ll[4];
        #pragma unroll
        for (int j = 0; j < 4; j++) split_bf16(Oacc[i][j] * inv, hh[j], ll[j]);
        size_t o = obase + (size_t)(q0 + 4 * ty + i) * EMB + 4 * tx;
        *(uint2*)&Oh[o] = *(uint2*)hh;
        *(uint2*)&Ol[o] = *(uint2*)ll;
    }
}

// ---------------- launch ----------------
extern "C" void kernel_launch(void* const* d_in, const int* in_sizes, int n_in,
                              void* d_out, int out_size)
{
    const float* x      = (const float*)d_in[0];
    const unsigned char* mask = (const unsigned char*)d_in[1];
    const float* wq     = (const float*)d_in[2];
    const float* wk     = (const float*)d_in[3];
    const float* wv     = (const float*)d_in[4];
    const float* proj_w = (const float*)d_in[5];
    const float* proj_b = (const float*)d_in[6];
    const float* ff_w1  = (const float*)d_in[7];
    const float* ff_b1  = (const float*)d_in[8];
    const float* ff_w2  = (const float*)d_in[9];
    const float* ff_b2  = (const float*)d_in[10];
    const float* ln1w   = (const float*)d_in[11];
    const float* ln1b   = (const float*)d_in[12];
    const float* ln2w   = (const float*)d_in[13];
    const float* ln2b   = (const float*)d_in[14];
    float* out = (float*)d_out;

    __nv_bfloat16 *ahi, *alo, *ffh, *ffl;
    __nv_bfloat16 *wqkvh, *wqkvl, *wprojh, *wprojl, *wff1h, *wff1l, *wff2h, *wff2l;
    float *qkv, *x1;
    cudaGetSymbolAddress((void**)&ahi, g_ahi);   cudaGetSymbolAddress((void**)&alo, g_alo);
    cudaGetSymbolAddress((void**)&ffh, g_ffhi);  cudaGetSymbolAddress((void**)&ffl, g_fflo);
    cudaGetSymbolAddress((void**)&wqkvh, g_wqkvh); cudaGetSymbolAddress((void**)&wqkvl, g_wqkvl);
    cudaGetSymbolAddress((void**)&wprojh, g_wprojh); cudaGetSymbolAddress((void**)&wprojl, g_wprojl);
    cudaGetSymbolAddress((void**)&wff1h, g_wff1h); cudaGetSymbolAddress((void**)&wff1l, g_wff1l);
    cudaGetSymbolAddress((void**)&wff2h, g_wff2h); cudaGetSymbolAddress((void**)&wff2l, g_wff2l);
    cudaGetSymbolAddress((void**)&qkv, g_qkv);   cudaGetSymbolAddress((void**)&x1, g_x1);

    cudaFuncSetAttribute(gemm_mma, cudaFuncAttributeMaxDynamicSharedMemorySize, GEMM_SMEM);
    cudaFuncSetAttribute(attn_kernel, cudaFuncAttributeMaxDynamicSharedMemorySize, ATTN_SMEM);

    lengths_kernel<<<1, 256>>>(mask);

    // weight prep: transpose + hi/lo split
    wsplit_kernel<<<dim3(EMB/32, EMB/32), 256>>>(wq, wqkvh, wqkvl, EMB, EMB, 0,      EMB);
    wsplit_kernel<<<dim3(EMB/32, EMB/32), 256>>>(wk, wqkvh, wqkvl, EMB, EMB, EMB,    EMB);
    wsplit_kernel<<<dim3(EMB/32, EMB/32), 256>>>(wv, wqkvh, wqkvl, EMB, EMB, 2*EMB,  EMB);
    wsplit_kernel<<<dim3(EMB/32, EMB/32), 256>>>(proj_w, wprojh, wprojl, EMB, EMB, 0, EMB);
    wsplit_kernel<<<dim3(DFF/32, EMB/32), 256>>>(ff_w1, wff1h, wff1l, EMB, DFF, 0,   EMB);
    wsplit_kernel<<<dim3(EMB/32, DFF/32), 256>>>(ff_w2, wff2h, wff2l, DFF, EMB, 0,   DFF);

    // h = LN1(x)*m (split)
    ln_split_kernel<<<MROWS, 256>>>(x, ln1w, ln1b, ahi, alo);

    // qkv = h @ Wqkv^T   [8192 x 3072]
    gemm_mma<<<dim3(QKVW/128, MROWS/128), 256, GEMM_SMEM>>>(
        ahi, alo, wqkvh, wqkvl, nullptr, nullptr, qkv, nullptr, nullptr,
        EMB, QKVW, 0, 0);

    // attention -> split output into ahi/alo
    attn_kernel<<<dim3(SEQ/64, NH, BATCH), 256, ATTN_SMEM>>>(qkv, ahi, alo);

    // x1 = x + attn @ proj_w + proj_b
    gemm_mma<<<dim3(EMB/128, MROWS/128), 256, GEMM_SMEM>>>(
        ahi, alo, wprojh, wprojl, x, proj_b, x1, nullptr, nullptr,
        EMB, EMB, 0, 0);

    // h2 = LN2(x1)*m (split)
    ln_split_kernel<<<MROWS, 256>>>(x1, ln2w, ln2b, ahi, alo);

    // ff = relu(h2 @ ff_w1 + b1) -> bf16 hi/lo
    gemm_mma<<<dim3(DFF/128, MROWS/128), 256, GEMM_SMEM>>>(
        ahi, alo, wff1h, wff1l, nullptr, ff_b1, nullptr, ffh, ffl,
        EMB, DFF, 1, 0);

    // out = (x1 + ff @ ff_w2 + b2) * m
    gemm_mma<<<dim3(EMB/128, MROWS/128), 256, GEMM_SMEM>>>(
        ffh, ffl, wff2h, wff2l, x1, ff_b2, out, nullptr, nullptr,
        DFF, EMB, 0, 1);
}

// round 9
// speedup vs baseline: 2.0027x; 1.3811x over previous
#include <cuda_runtime.h>
#include <cuda_bf16.h>
#include <math.h>
#include <stdint.h>

#define BATCH 4
#define SEQ   2048
#define EMB   1024
#define NH    16
#define HS    64
#define DFF   4096
#define MROWS (BATCH*SEQ)   // 8192
#define QKVW  (3*EMB)       // 3072

// ---------------- scratch (device globals; no allocation) ----------------
__device__ __align__(256) __nv_bfloat16 g_ahi [MROWS*EMB];
__device__ __align__(256) __nv_bfloat16 g_alo [MROWS*EMB];
__device__ __align__(256) __nv_bfloat16 g_ffhi[MROWS*DFF];
__device__ __align__(256) __nv_bfloat16 g_fflo[MROWS*DFF];
__device__ __align__(256) __nv_bfloat16 g_qkvh[MROWS*QKVW];
__device__ __align__(256) __nv_bfloat16 g_qkvl[MROWS*QKVW];
__device__ __align__(256) __nv_bfloat16 g_wqkvh[QKVW*EMB];
__device__ __align__(256) __nv_bfloat16 g_wqkvl[QKVW*EMB];
__device__ __align__(256) __nv_bfloat16 g_wprojh[EMB*EMB];
__device__ __align__(256) __nv_bfloat16 g_wprojl[EMB*EMB];
__device__ __align__(256) __nv_bfloat16 g_wff1h[DFF*EMB];
__device__ __align__(256) __nv_bfloat16 g_wff1l[DFF*EMB];
__device__ __align__(256) __nv_bfloat16 g_wff2h[EMB*DFF];
__device__ __align__(256) __nv_bfloat16 g_wff2l[EMB*DFF];
__device__ __align__(256) float g_x1 [MROWS*EMB];
__device__ int g_len[BATCH];

// ---------------- helpers ----------------
__device__ __forceinline__ uint32_t smem_u32(const void* p) {
    uint32_t a;
    asm("{ .reg .u64 t; cvta.to.shared.u64 t, %1; cvt.u32.u64 %0, t; }" : "=r"(a) : "l"(p));
    return a;
}
__device__ __forceinline__ void cp_async16(uint32_t dst, const void* src) {
    asm volatile("cp.async.cg.shared.global [%0], [%1], 16;\n" :: "r"(dst), "l"(src));
}
#define CP_COMMIT() asm volatile("cp.async.commit_group;\n" ::: "memory")
#define CP_WAIT0()  asm volatile("cp.async.wait_group 0;\n" ::: "memory")
#define CP_WAIT1()  asm volatile("cp.async.wait_group 1;\n" ::: "memory")

__device__ __forceinline__ void ldsm4(uint32_t* r, uint32_t addr) {
    asm volatile("ldmatrix.sync.aligned.m8n8.x4.shared.b16 {%0,%1,%2,%3}, [%4];"
        : "=r"(r[0]), "=r"(r[1]), "=r"(r[2]), "=r"(r[3]) : "r"(addr));
}
__device__ __forceinline__ void ldsm4t(uint32_t* r, uint32_t addr) {
    asm volatile("ldmatrix.sync.aligned.m8n8.x4.trans.shared.b16 {%0,%1,%2,%3}, [%4];"
        : "=r"(r[0]), "=r"(r[1]), "=r"(r[2]), "=r"(r[3]) : "r"(addr));
}
__device__ __forceinline__ void mma_bf16(float* d, const uint32_t* a, const uint32_t* b) {
    asm volatile("mma.sync.aligned.m16n8k16.row.col.f32.bf16.bf16.f32 "
        "{%0,%1,%2,%3}, {%4,%5,%6,%7}, {%8,%9}, {%0,%1,%2,%3};"
        : "+f"(d[0]), "+f"(d[1]), "+f"(d[2]), "+f"(d[3])
        : "r"(a[0]), "r"(a[1]), "r"(a[2]), "r"(a[3]), "r"(b[0]), "r"(b[1]));
}
__device__ __forceinline__ uint32_t sw128(uint32_t off) {
    return off ^ ((off >> 3) & 0x70);
}
__device__ __forceinline__ void split_bf16(float v, __nv_bfloat16& h, __nv_bfloat16& l) {
    h = __float2bfloat16(v);
    l = __float2bfloat16(v - __bfloat162float(h));
}
// split pair (a,b) into packed hi bf16x2 and lo bf16x2 (a in low half)
__device__ __forceinline__ void split2(float a, float b, uint32_t& hi, uint32_t& lo) {
    __nv_bfloat16 ha = __float2bfloat16(a), hb = __float2bfloat16(b);
    __nv_bfloat162 hh; hh.x = ha; hh.y = hb;
    hi = *(uint32_t*)&hh;
    __nv_bfloat162 ll;
    ll.x = __float2bfloat16(a - __bfloat162float(ha));
    ll.y = __float2bfloat16(b - __bfloat162float(hb));
    lo = *(uint32_t*)&ll;
}

// ---------------- lengths from key_padding_mask (dtype-robust) ----------------
__global__ void lengths_kernel(const unsigned char* mraw) {
    __shared__ int s_cnt[BATCH];
    __shared__ int s_isbool;
    int tid = threadIdx.x;
    if (tid < BATCH) s_cnt[tid] = 0;
    if (tid == 0) s_isbool = (mraw[1] | mraw[2] | mraw[3]) ? 1 : 0;
    __syncthreads();
    for (int b = 0; b < BATCH; b++) {
        int c = 0;
        if (s_isbool) {
            const unsigned char* p = mraw + (size_t)b * SEQ;
            for (int t = tid; t < SEQ; t += blockDim.x) c += p[t] ? 1 : 0;
        } else {
            const int* p = (const int*)mraw + (size_t)b * SEQ;
            for (int t = tid; t < SEQ; t += blockDim.x) c += p[t] ? 1 : 0;
        }
        atomicAdd(&s_cnt[b], c);
    }
    __syncthreads();
    if (tid < BATCH) g_len[tid] = s_cnt[tid];
}

// ---------------- weight transpose + hi/lo split: W[K,N] -> T[N,K] bf16 x2 ----------------
__global__ void __launch_bounds__(256) wsplit_kernel(
    const float* __restrict__ W, __nv_bfloat16* __restrict__ Th,
    __nv_bfloat16* __restrict__ Tl, int K, int N, int rowOff, int ldt)
{
    __shared__ float t[32][33];
    int n0 = blockIdx.x * 32, k0 = blockIdx.y * 32;
    int tx = threadIdx.x & 31, ty = threadIdx.x >> 5;
    #pragma unroll
    for (int i = 0; i < 32; i += 8)
        t[ty + i][tx] = W[(size_t)(k0 + ty + i) * N + n0 + tx];
    __syncthreads();
    #pragma unroll
    for (int i = 0; i < 32; i += 8) {
        float v = t[tx][ty + i];
        size_t o = (size_t)(rowOff + n0 + ty + i) * ldt + k0 + tx;
        __nv_bfloat16 h, l; split_bf16(v, h, l);
        Th[o] = h; Tl[o] = l;
    }
}

// ---------------- LayerNorm -> masked, bf16 hi/lo split output ----------------
__global__ void __launch_bounds__(256) ln_split_kernel(
    const float* __restrict__ x, const float* __restrict__ w,
    const float* __restrict__ bia, __nv_bfloat16* __restrict__ yh,
    __nv_bfloat16* __restrict__ yl)
{
    int row = blockIdx.x;
    int b = row >> 11, t = row & (SEQ - 1);
    const float* xr = x + (size_t)row * EMB;
    float s = 0.f, sq = 0.f;
    for (int i = threadIdx.x; i < EMB; i += 256) { float v = xr[i]; s += v; sq += v * v; }
    #pragma unroll
    for (int o = 16; o; o >>= 1) {
        s  += __shfl_xor_sync(~0u, s,  o);
        sq += __shfl_xor_sync(~0u, sq, o);
    }
    __shared__ float red[16];
    __shared__ float s_mu, s_rstd;
    int wid = threadIdx.x >> 5, lid = threadIdx.x & 31;
    if (lid == 0) { red[wid] = s; red[8 + wid] = sq; }
    __syncthreads();
    if (threadIdx.x == 0) {
        float S = 0.f, SQ = 0.f;
        for (int i = 0; i < 8; i++) { S += red[i]; SQ += red[8 + i]; }
        float mu = S * (1.f / EMB);
        float var = SQ * (1.f / EMB) - mu * mu;
        s_mu = mu; s_rstd = rsqrtf(var + 1e-5f);
    }
    __syncthreads();
    float mk = (t < g_len[b]) ? 1.f : 0.f;
    float mu = s_mu, rstd = s_rstd;
    for (int i = threadIdx.x; i < EMB; i += 256) {
        float v = ((xr[i] - mu) * rstd * w[i] + bia[i]) * mk;
        __nv_bfloat16 h, l; split_bf16(v, h, l);
        yh[(size_t)row * EMB + i] = h;
        yl[(size_t)row * EMB + i] = l;
    }
}

// ---------------- mma.sync GEMM, 3-stage cp.async pipeline ----------------
// C[M,N] = A @ B^T (split-bf16, fp32 acc). 128x128 tile, 8 warps (2x4).
#define GEMM_SMEM (3 * 65536)

__global__ void __launch_bounds__(256) gemm_mma(
    const __nv_bfloat16* __restrict__ Ahi, const __nv_bfloat16* __restrict__ Alo,
    const __nv_bfloat16* __restrict__ Bhi, const __nv_bfloat16* __restrict__ Blo,
    const float* __restrict__ Res, const float* __restrict__ Bias,
    float* __restrict__ Cf, __nv_bfloat16* __restrict__ Chi, __nv_bfloat16* __restrict__ Clo,
    int K, int ldc, int doRelu, int doMask)
{
    extern __shared__ char smem[];
    uint32_t sb = smem_u32(smem);
    int tid = threadIdx.x;
    int lane = tid & 31, wid = tid >> 5;
    int wm = (wid >> 2) * 64;
    int wn = (wid & 3) * 32;
    int m0 = blockIdx.y * 128, n0 = blockIdx.x * 128;

    int nc = K >> 6;

    auto load_chunk = [&](uint32_t st, int kc) {
        #pragma unroll
        for (int i = 0; i < 4; i++) {
            int g = tid + i * 256;
            int r = g >> 3, c16 = g & 7;
            uint32_t sw = sw128(r * 128 + c16 * 16);
            size_t ao = (size_t)(m0 + r) * K + kc + c16 * 8;
            size_t bo = (size_t)(n0 + r) * K + kc + c16 * 8;
            cp_async16(st + 0 * 16384 + sw, Ahi + ao);
            cp_async16(st + 1 * 16384 + sw, Alo + ao);
            cp_async16(st + 2 * 16384 + sw, Bhi + bo);
            cp_async16(st + 3 * 16384 + sw, Blo + bo);
        }
        CP_COMMIT();
    };

    int grp = lane >> 3, lrow = lane & 7;
    int a_r = lrow + ((grp & 1) ? 8 : 0);
    int a_c = grp >> 1;
    int b_r = lrow + ((grp >> 1) ? 8 : 0);
    int b_c = grp & 1;

    float d[4][4][4];
    #pragma unroll
    for (int i = 0; i < 4; i++)
        #pragma unroll
        for (int j = 0; j < 4; j++)
            #pragma unroll
            for (int q = 0; q < 4; q++) d[i][j][q] = 0.f;

    load_chunk(sb, 0);
    load_chunk(sb + 65536, 64);
    CP_WAIT1();
    __syncthreads();

    for (int c = 0; c < nc; c++) {
        uint32_t st = sb + (c % 3) * 65536;
        if (c + 2 < nc) load_chunk(sb + ((c + 2) % 3) * 65536, (c + 2) * 64);

        #pragma unroll
        for (int ks = 0; ks < 4; ks++) {
            uint32_t ah[4][4], al[4][4], bh[4][2], bl[4][2];
            #pragma unroll
            for (int mt = 0; mt < 4; mt++) {
                uint32_t off = sw128((wm + mt * 16 + a_r) * 128 + (2 * ks + a_c) * 16);
                ldsm4(ah[mt], st + off);
                ldsm4(al[mt], st + 16384 + off);
            }
            #pragma unroll
            for (int np = 0; np < 2; np++) {
                uint32_t off = sw128((wn + np * 16 + b_r) * 128 + (2 * ks + b_c) * 16);
                uint32_t th[4], tl[4];
                ldsm4(th, st + 32768 + off);
                ldsm4(tl, st + 49152 + off);
                bh[np * 2][0] = th[0]; bh[np * 2][1] = th[1];
                bh[np * 2 + 1][0] = th[2]; bh[np * 2 + 1][1] = th[3];
                bl[np * 2][0] = tl[0]; bl[np * 2][1] = tl[1];
                bl[np * 2 + 1][0] = tl[2]; bl[np * 2 + 1][1] = tl[3];
            }
            #pragma unroll
            for (int mt = 0; mt < 4; mt++)
                #pragma unroll
                for (int nt = 0; nt < 4; nt++) {
                    mma_bf16(d[mt][nt], ah[mt], bh[nt]);
                    mma_bf16(d[mt][nt], ah[mt], bl[nt]);
                    mma_bf16(d[mt][nt], al[mt], bh[nt]);
                }
        }
        if (c + 2 < nc) CP_WAIT1(); else CP_WAIT0();
        __syncthreads();
    }

    // ---- epilogue: stage f32 accum through smem ----
    float* eb = (float*)smem;    // [128][132]
    int fr = lane >> 2, fc = (lane & 3) * 2;
    #pragma unroll
    for (int mt = 0; mt < 4; mt++)
        #pragma unroll
        for (int nt = 0; nt < 4; nt++) {
            int rr = wm + mt * 16 + fr;
            int cc = wn + nt * 8 + fc;
            *(float2*)&eb[rr * 132 + cc]       = make_float2(d[mt][nt][0], d[mt][nt][1]);
            *(float2*)&eb[(rr + 8) * 132 + cc] = make_float2(d[mt][nt][2], d[mt][nt][3]);
        }
    __syncthreads();

    #pragma unroll
    for (int it = 0; it < 16; it++) {
        int idx = tid + it * 256;
        int rr = idx >> 5;
        int cc = (idx & 31) * 4;
        int m = m0 + rr, n = n0 + cc;
        float4 v = *(float4*)&eb[rr * 132 + cc];
        if (Bias) {
            v.x += Bias[n]; v.y += Bias[n + 1]; v.z += Bias[n + 2]; v.w += Bias[n + 3];
        }
        if (Res) {
            float4 rv = *(const float4*)&Res[(size_t)m * ldc + n];
            v.x += rv.x; v.y += rv.y; v.z += rv.z; v.w += rv.w;
        }
        if (doRelu) {
            v.x = fmaxf(v.x, 0.f); v.y = fmaxf(v.y, 0.f);
            v.z = fmaxf(v.z, 0.f); v.w = fmaxf(v.w, 0.f);
        }
        if (doMask) {
            int bb = m >> 11, t = m & (SEQ - 1);
            float mk = (t < g_len[bb]) ? 1.f : 0.f;
            v.x *= mk; v.y *= mk; v.z *= mk; v.w *= mk;
        }
        if (Chi) {
            __nv_bfloat16 h[4], l[4];
            split_bf16(v.x, h[0], l[0]); split_bf16(v.y, h[1], l[1]);
            split_bf16(v.z, h[2], l[2]); split_bf16(v.w, h[3], l[3]);
            *(uint2*)&Chi[(size_t)m * ldc + n] = *(uint2*)h;
            *(uint2*)&Clo[(size_t)m * ldc + n] = *(uint2*)l;
        } else {
            *(float4*)&Cf[(size_t)m * ldc + n] = v;
        }
    }
}

// ---------------- Flash attention with split-bf16 mma.sync ----------------
// 64q x 64k tiles, 4 warps (16 q-rows each), softmax in registers.
#define ATTN_SMEM (6 * 8192)

__global__ void __launch_bounds__(128) attn_mma_kernel(
    const __nv_bfloat16* __restrict__ QKVh, const __nv_bfloat16* __restrict__ QKVl,
    __nv_bfloat16* __restrict__ Oh, __nv_bfloat16* __restrict__ Ol)
{
    extern __shared__ char smem[];
    uint32_t sb = smem_u32(smem);
    const uint32_t sQh = sb, sQl = sb + 8192, sKh = sb + 16384, sKl = sb + 24576,
                   sVh = sb + 32768, sVl = sb + 40960;
    int tid = threadIdx.x, lane = tid & 31, wid = tid >> 5;
    int b = blockIdx.z, h = blockIdx.y, qt = blockIdx.x;
    int q0 = qt * 64;
    int len = g_len[b];
    size_t rowbase = (size_t)b * SEQ;
    int cq = h * HS, ck = EMB + h * HS, cv = 2 * EMB + h * HS;

    // load Q tile (hi/lo), SW128
    #pragma unroll
    for (int i = 0; i < 4; i++) {
        int idx = tid + i * 128;
        int r = idx >> 3, c16 = idx & 7;
        uint32_t sw = sw128(r * 128 + c16 * 16);
        size_t g = (rowbase + q0 + r) * QKVW + cq + c16 * 8;
        cp_async16(sQh + sw, QKVh + g);
        cp_async16(sQl + sw, QKVl + g);
    }
    CP_COMMIT();

    float Oacc[8][4];
    #pragma unroll
    for (int j = 0; j < 8; j++)
        #pragma unroll
        for (int q = 0; q < 4; q++) Oacc[j][q] = 0.f;
    float mrow0 = -1e30f, mrow1 = -1e30f, lrow0 = 0.f, lrow1 = 0.f;

    const float scale = 0.03125f;  // 1024^-0.5
    int lenTiles = (len + 63) >> 6;
    int nT = min(qt + 1, lenTiles);

    int l15 = lane & 15, lh = lane >> 4;
    int grp = lane >> 3, lrow = lane & 7;
    int b_r = lrow + ((grp >> 1) ? 8 : 0);   // B-operand lane addressing (as in gemm)
    int b_c = grp & 1;
    int wq = wid * 16;
    int r0 = q0 + wq + (lane >> 2);   // global seq row of d0,d1 (row+8 for d2,d3)
    int dlo = (lane & 3) * 2;

    for (int kt = 0; kt < nT; kt++) {
        int s0 = kt * 64;
        __syncthreads();   // all warps done reading previous K/V
        #pragma unroll
        for (int i = 0; i < 4; i++) {
            int idx = tid + i * 128;
            int r = idx >> 3, c16 = idx & 7;
            uint32_t sw = sw128(r * 128 + c16 * 16);
            size_t gk = (rowbase + s0 + r) * QKVW + ck + c16 * 8;
            size_t gv = (rowbase + s0 + r) * QKVW + cv + c16 * 8;
            cp_async16(sKh + sw, QKVh + gk);
            cp_async16(sKl + sw, QKVl + gk);
            cp_async16(sVh + sw, QKVh + gv);
            cp_async16(sVl + sw, QKVl + gv);
        }
        CP_COMMIT();
        CP_WAIT0();
        __syncthreads();

        // ---- S = Q K^T (3-term split), fp32 frags ----
        float sacc[8][4];
        #pragma unroll
        for (int j = 0; j < 8; j++)
            #pragma unroll
            for (int q = 0; q < 4; q++) sacc[j][q] = 0.f;

        #pragma unroll
        for (int ks = 0; ks < 4; ks++) {
            uint32_t qh[4], ql[4];
            uint32_t aoff = sw128((wq + l15) * 128 + (ks * 2 + lh) * 16);
            ldsm4(qh, sQh + aoff);
            ldsm4(ql, sQl + aoff);
            #pragma unroll
            for (int np = 0; np < 4; np++) {
                // B-operand addressing: pairs {kh[0],kh[1]} = n rows np*16+0..7 (k0,k1),
                // {kh[2],kh[3]} = n rows np*16+8..15
                uint32_t boff = sw128((np * 16 + b_r) * 128 + (ks * 2 + b_c) * 16);
                uint32_t kh[4], kl[4];
                ldsm4(kh, sKh + boff);
                ldsm4(kl, sKl + boff);
                mma_bf16(sacc[np * 2],     qh, &kh[0]);
                mma_bf16(sacc[np * 2],     qh, &kl[0]);
                mma_bf16(sacc[np * 2],     ql, &kh[0]);
                mma_bf16(sacc[np * 2 + 1], qh, &kh[2]);
                mma_bf16(sacc[np * 2 + 1], qh, &kl[2]);
                mma_bf16(sacc[np * 2 + 1], ql, &kh[2]);
            }
        }

        // ---- scale + mask + row max ----
        float rmax0 = -1e30f, rmax1 = -1e30f;
        #pragma unroll
        for (int j = 0; j < 8; j++) {
            int kj = s0 + j * 8 + dlo;
            #pragma unroll
            for (int q = 0; q < 4; q++) {
                int col = kj + (q & 1);
                int row = r0 + (q >> 1) * 8;
                float v = sacc[j][q] * scale;
                if (col > row || col >= len) v = -1e30f;
                sacc[j][q] = v;
            }
            rmax0 = fmaxf(rmax0, fmaxf(sacc[j][0], sacc[j][1]));
            rmax1 = fmaxf(rmax1, fmaxf(sacc[j][2], sacc[j][3]));
        }
        rmax0 = fmaxf(rmax0, __shfl_xor_sync(~0u, rmax0, 1));
        rmax0 = fmaxf(rmax0, __shfl_xor_sync(~0u, rmax0, 2));
        rmax1 = fmaxf(rmax1, __shfl_xor_sync(~0u, rmax1, 1));
        rmax1 = fmaxf(rmax1, __shfl_xor_sync(~0u, rmax1, 2));

        float mnew0 = fmaxf(mrow0, rmax0), mnew1 = fmaxf(mrow1, rmax1);
        float corr0 = __expf(mrow0 - mnew0), corr1 = __expf(mrow1 - mnew1);
        mrow0 = mnew0; mrow1 = mnew1;

        // ---- P = exp(S - m), row sums ----
        float rsum0 = 0.f, rsum1 = 0.f;
        #pragma unroll
        for (int j = 0; j < 8; j++) {
            sacc[j][0] = __expf(sacc[j][0] - mnew0);
            sacc[j][1] = __expf(sacc[j][1] - mnew0);
            sacc[j][2] = __expf(sacc[j][2] - mnew1);
            sacc[j][3] = __expf(sacc[j][3] - mnew1);
            rsum0 += sacc[j][0] + sacc[j][1];
            rsum1 += sacc[j][2] + sacc[j][3];
        }
        rsum0 += __shfl_xor_sync(~0u, rsum0, 1);
        rsum0 += __shfl_xor_sync(~0u, rsum0, 2);
        rsum1 += __shfl_xor_sync(~0u, rsum1, 1);
        rsum1 += __shfl_xor_sync(~0u, rsum1, 2);
        lrow0 = lrow0 * corr0 + rsum0;
        lrow1 = lrow1 * corr1 + rsum1;

        // ---- rescale O ----
        #pragma unroll
        for (int j = 0; j < 8; j++) {
            Oacc[j][0] *= corr0; Oacc[j][1] *= corr0;
            Oacc[j][2] *= corr1; Oacc[j][3] *= corr1;
        }

        // ---- O += P @ V (3-term split), V via ldmatrix.trans ----
        #pragma unroll
        for (int ks = 0; ks < 4; ks++) {
            int j0 = 2 * ks, j1 = j0 + 1;
            uint32_t ph[4], pl[4];
            split2(sacc[j0][0], sacc[j0][1], ph[0], pl[0]);
            split2(sacc[j0][2], sacc[j0][3], ph[1], pl[1]);
            split2(sacc[j1][0], sacc[j1][1], ph[2], pl[2]);
            split2(sacc[j1][2], sacc[j1][3], ph[3], pl[3]);
            #pragma unroll
            for (int dg = 0; dg < 4; dg++) {
                uint32_t voff = sw128((ks * 16 + l15) * 128 + (dg * 2 + lh) * 16);
                uint32_t vh[4], vl[4];
                ldsm4t(vh, sVh + voff);
                ldsm4t(vl, sVl + voff);
                mma_bf16(Oacc[dg * 2],     ph, &vh[0]);
                mma_bf16(Oacc[dg * 2],     ph, &vl[0]);
                mma_bf16(Oacc[dg * 2],     pl, &vh[0]);
                mma_bf16(Oacc[dg * 2 + 1], ph, &vh[2]);
                mma_bf16(Oacc[dg * 2 + 1], ph, &vl[2]);
                mma_bf16(Oacc[dg * 2 + 1], pl, &vh[2]);
            }
        }
    }

    // ---- final: O /= l, write bf16 hi/lo ----
    float inv0 = 1.f / lrow0, inv1 = 1.f / lrow1;
    size_t row0 = rowbase + r0, row1 = row0 + 8;
    #pragma unroll
    for (int j = 0; j < 8; j++) {
        int dc = h * HS + j * 8 + dlo;
        uint32_t uh, ul;
        split2(Oacc[j][0] * inv0, Oacc[j][1] * inv0, uh, ul);
        *(uint32_t*)&Oh[row0 * EMB + dc] = uh;
        *(uint32_t*)&Ol[row0 * EMB + dc] = ul;
        split2(Oacc[j][2] * inv1, Oacc[j][3] * inv1, uh, ul);
        *(uint32_t*)&Oh[row1 * EMB + dc] = uh;
        *(uint32_t*)&Ol[row1 * EMB + dc] = ul;
    }
}

// ---------------- launch ----------------
extern "C" void kernel_launch(void* const* d_in, const int* in_sizes, int n_in,
                              void* d_out, int out_size)
{
    const float* x      = (const float*)d_in[0];
    const unsigned char* mask = (const unsigned char*)d_in[1];
    const float* wq     = (const float*)d_in[2];
    const float* wk     = (const float*)d_in[3];
    const float* wv     = (const float*)d_in[4];
    const float* proj_w = (const float*)d_in[5];
    const float* proj_b = (const float*)d_in[6];
    const float* ff_w1  = (const float*)d_in[7];
    const float* ff_b1  = (const float*)d_in[8];
    const float* ff_w2  = (const float*)d_in[9];
    const float* ff_b2  = (const float*)d_in[10];
    const float* ln1w   = (const float*)d_in[11];
    const float* ln1b   = (const float*)d_in[12];
    const float* ln2w   = (const float*)d_in[13];
    const float* ln2b   = (const float*)d_in[14];
    float* out = (float*)d_out;

    __nv_bfloat16 *ahi, *alo, *ffh, *ffl, *qkvh, *qkvl;
    __nv_bfloat16 *wqkvh, *wqkvl, *wprojh, *wprojl, *wff1h, *wff1l, *wff2h, *wff2l;
    float *x1;
    cudaGetSymbolAddress((void**)&ahi, g_ahi);   cudaGetSymbolAddress((void**)&alo, g_alo);
    cudaGetSymbolAddress((void**)&ffh, g_ffhi);  cudaGetSymbolAddress((void**)&ffl, g_fflo);
    cudaGetSymbolAddress((void**)&qkvh, g_qkvh); cudaGetSymbolAddress((void**)&qkvl, g_qkvl);
    cudaGetSymbolAddress((void**)&wqkvh, g_wqkvh); cudaGetSymbolAddress((void**)&wqkvl, g_wqkvl);
    cudaGetSymbolAddress((void**)&wprojh, g_wprojh); cudaGetSymbolAddress((void**)&wprojl, g_wprojl);
    cudaGetSymbolAddress((void**)&wff1h, g_wff1h); cudaGetSymbolAddress((void**)&wff1l, g_wff1l);
    cudaGetSymbolAddress((void**)&wff2h, g_wff2h); cudaGetSymbolAddress((void**)&wff2l, g_wff2l);
    cudaGetSymbolAddress((void**)&x1, g_x1);

    cudaFuncSetAttribute(gemm_mma, cudaFuncAttributeMaxDynamicSharedMemorySize, GEMM_SMEM);
    cudaFuncSetAttribute(attn_mma_kernel, cudaFuncAttributeMaxDynamicSharedMemorySize, ATTN_SMEM);

    lengths_kernel<<<1, 256>>>(mask);

    // weight prep: transpose + hi/lo split
    wsplit_kernel<<<dim3(EMB/32, EMB/32), 256>>>(wq, wqkvh, wqkvl, EMB, EMB, 0,      EMB);
    wsplit_kernel<<<dim3(EMB/32, EMB/32), 256>>>(wk, wqkvh, wqkvl, EMB, EMB, EMB,    EMB);
    wsplit_kernel<<<dim3(EMB/32, EMB/32), 256>>>(wv, wqkvh, wqkvl, EMB, EMB, 2*EMB,  EMB);
    wsplit_kernel<<<dim3(EMB/32, EMB/32), 256>>>(proj_w, wprojh, wprojl, EMB, EMB, 0, EMB);
    wsplit_kernel<<<dim3(DFF/32, EMB/32), 256>>>(ff_w1, wff1h, wff1l, EMB, DFF, 0,   EMB);
    wsplit_kernel<<<dim3(EMB/32, DFF/32), 256>>>(ff_w2, wff2h, wff2l, DFF, EMB, 0,   DFF);

    // h = LN1(x)*m (split)
    ln_split_kernel<<<MROWS, 256>>>(x, ln1w, ln1b, ahi, alo);

    // qkv = h @ Wqkv^T -> bf16 hi/lo  [8192 x 3072]
    gemm_mma<<<dim3(QKVW/128, MROWS/128), 256, GEMM_SMEM>>>(
        ahi, alo, wqkvh, wqkvl, nullptr, nullptr, nullptr, qkvh, qkvl,
        EMB, QKVW, 0, 0);

    // attention (tensor-core flash) -> ahi/alo
    attn_mma_kernel<<<dim3(SEQ/64, NH, BATCH), 128, ATTN_SMEM>>>(qkvh, qkvl, ahi, alo);

    // x1 = x + attn @ proj_w + proj_b
    gemm_mma<<<dim3(EMB/128, MROWS/128), 256, GEMM_SMEM>>>(
        ahi, alo, wprojh, wprojl, x, proj_b, x1, nullptr, nullptr,
        EMB, EMB, 0, 0);

    // h2 = LN2(x1)*m (split)
    ln_split_kernel<<<MROWS, 256>>>(x1, ln2w, ln2b, ahi, alo);

    // ff = relu(h2 @ ff_w1 + b1) -> bf16 hi/lo
    gemm_mma<<<dim3(DFF/128, MROWS/128), 256, GEMM_SMEM>>>(
        ahi, alo, wff1h, wff1l, nullptr, ff_b1, nullptr, ffh, ffl,
        EMB, DFF, 1, 0);

    // out = (x1 + ff @ ff_w2 + b2) * m
    gemm_mma<<<dim3(EMB/128, MROWS/128), 256, GEMM_SMEM>>>(
        ffh, ffl, wff2h, wff2l, x1, ff_b2, out, nullptr, nullptr,
        DFF, EMB, 0, 1);
}

// round 10
// speedup vs baseline: 3.2064x; 1.6010x over previous
#include <cuda_runtime.h>
#include <cuda_bf16.h>
#include <math.h>
#include <stdint.h>

#define BATCH 4
#define SEQ   2048
#define EMB   1024
#define NH    16
#define HS    64
#define DFF   4096
#define MROWS (BATCH*SEQ)   // 8192
#define QKVW  (3*EMB)       // 3072

// ---------------- scratch (device globals; no allocation) ----------------
__device__ __align__(256) __nv_bfloat16 g_ahi [MROWS*EMB];
__device__ __align__(256) __nv_bfloat16 g_alo [MROWS*EMB];
__device__ __align__(256) __nv_bfloat16 g_ffhi[MROWS*DFF];
__device__ __align__(256) __nv_bfloat16 g_fflo[MROWS*DFF];
__device__ __align__(256) __nv_bfloat16 g_qkvh[MROWS*QKVW];
__device__ __align__(256) __nv_bfloat16 g_qkvl[MROWS*QKVW];
__device__ __align__(256) __nv_bfloat16 g_wqkvh[QKVW*EMB];
__device__ __align__(256) __nv_bfloat16 g_wqkvl[QKVW*EMB];
__device__ __align__(256) __nv_bfloat16 g_wprojh[EMB*EMB];
__device__ __align__(256) __nv_bfloat16 g_wprojl[EMB*EMB];
__device__ __align__(256) __nv_bfloat16 g_wff1h[DFF*EMB];
__device__ __align__(256) __nv_bfloat16 g_wff1l[DFF*EMB];
__device__ __align__(256) __nv_bfloat16 g_wff2h[EMB*DFF];
__device__ __align__(256) __nv_bfloat16 g_wff2l[EMB*DFF];
__device__ __align__(256) float g_x1 [MROWS*EMB];
__device__ int g_len[BATCH];

// ---------------- helpers ----------------
__device__ __forceinline__ uint32_t smem_u32(const void* p) {
    uint32_t a;
    asm("{ .reg .u64 t; cvta.to.shared.u64 t, %1; cvt.u32.u64 %0, t; }" : "=r"(a) : "l"(p));
    return a;
}
__device__ __forceinline__ void cp_async16(uint32_t dst, const void* src) {
    asm volatile("cp.async.cg.shared.global [%0], [%1], 16;\n" :: "r"(dst), "l"(src));
}
#define CP_COMMIT() asm volatile("cp.async.commit_group;\n" ::: "memory")
#define CP_WAIT0()  asm volatile("cp.async.wait_group 0;\n" ::: "memory")
#define CP_WAIT1()  asm volatile("cp.async.wait_group 1;\n" ::: "memory")

__device__ __forceinline__ void ldsm4(uint32_t* r, uint32_t addr) {
    asm volatile("ldmatrix.sync.aligned.m8n8.x4.shared.b16 {%0,%1,%2,%3}, [%4];"
        : "=r"(r[0]), "=r"(r[1]), "=r"(r[2]), "=r"(r[3]) : "r"(addr));
}
__device__ __forceinline__ void ldsm4t(uint32_t* r, uint32_t addr) {
    asm volatile("ldmatrix.sync.aligned.m8n8.x4.trans.shared.b16 {%0,%1,%2,%3}, [%4];"
        : "=r"(r[0]), "=r"(r[1]), "=r"(r[2]), "=r"(r[3]) : "r"(addr));
}
__device__ __forceinline__ void mma_bf16(float* d, const uint32_t* a, const uint32_t* b) {
    asm volatile("mma.sync.aligned.m16n8k16.row.col.f32.bf16.bf16.f32 "
        "{%0,%1,%2,%3}, {%4,%5,%6,%7}, {%8,%9}, {%0,%1,%2,%3};"
        : "+f"(d[0]), "+f"(d[1]), "+f"(d[2]), "+f"(d[3])
        : "r"(a[0]), "r"(a[1]), "r"(a[2]), "r"(a[3]), "r"(b[0]), "r"(b[1]));
}
__device__ __forceinline__ uint32_t sw128(uint32_t off) {
    return off ^ ((off >> 3) & 0x70);
}
__device__ __forceinline__ void split_bf16(float v, __nv_bfloat16& h, __nv_bfloat16& l) {
    h = __float2bfloat16(v);
    l = __float2bfloat16(v - __bfloat162float(h));
}
// split pair (a,b) into packed hi bf16x2 and lo bf16x2 (a in low half)
__device__ __forceinline__ void split2(float a, float b, uint32_t& hi, uint32_t& lo) {
    __nv_bfloat16 ha = __float2bfloat16(a), hb = __float2bfloat16(b);
    __nv_bfloat162 hh; hh.x = ha; hh.y = hb;
    hi = *(uint32_t*)&hh;
    __nv_bfloat162 ll;
    ll.x = __float2bfloat16(a - __bfloat162float(ha));
    ll.y = __float2bfloat16(b - __bfloat162float(hb));
    lo = *(uint32_t*)&ll;
}

// ---------------- lengths from key_padding_mask (dtype-robust) ----------------
__global__ void lengths_kernel(const unsigned char* mraw) {
    __shared__ int s_cnt[BATCH];
    __shared__ int s_isbool;
    int tid = threadIdx.x;
    if (tid < BATCH) s_cnt[tid] = 0;
    if (tid == 0) s_isbool = (mraw[1] | mraw[2] | mraw[3]) ? 1 : 0;
    __syncthreads();
    for (int b = 0; b < BATCH; b++) {
        int c = 0;
        if (s_isbool) {
            const unsigned char* p = mraw + (size_t)b * SEQ;
            for (int t = tid; t < SEQ; t += blockDim.x) c += p[t] ? 1 : 0;
        } else {
            const int* p = (const int*)mraw + (size_t)b * SEQ;
            for (int t = tid; t < SEQ; t += blockDim.x) c += p[t] ? 1 : 0;
        }
        atomicAdd(&s_cnt[b], c);
    }
    __syncthreads();
    if (tid < BATCH) g_len[tid] = s_cnt[tid];
}

// ---------------- weight transpose + hi/lo split: W[K,N] -> T[N,K] bf16 x2 ----------------
__global__ void __launch_bounds__(256) wsplit_kernel(
    const float* __restrict__ W, __nv_bfloat16* __restrict__ Th,
    __nv_bfloat16* __restrict__ Tl, int K, int N, int rowOff, int ldt)
{
    __shared__ float t[32][33];
    int n0 = blockIdx.x * 32, k0 = blockIdx.y * 32;
    int tx = threadIdx.x & 31, ty = threadIdx.x >> 5;
    #pragma unroll
    for (int i = 0; i < 32; i += 8)
        t[ty + i][tx] = W[(size_t)(k0 + ty + i) * N + n0 + tx];
    __syncthreads();
    #pragma unroll
    for (int i = 0; i < 32; i += 8) {
        float v = t[tx][ty + i];
        size_t o = (size_t)(rowOff + n0 + ty + i) * ldt + k0 + tx;
        __nv_bfloat16 h, l; split_bf16(v, h, l);
        Th[o] = h; Tl[o] = l;
    }
}

// ---------------- LayerNorm -> masked, bf16 hi/lo split output ----------------
__global__ void __launch_bounds__(256) ln_split_kernel(
    const float* __restrict__ x, const float* __restrict__ w,
    const float* __restrict__ bia, __nv_bfloat16* __restrict__ yh,
    __nv_bfloat16* __restrict__ yl)
{
    int row = blockIdx.x;
    int b = row >> 11, t = row & (SEQ - 1);
    const float* xr = x + (size_t)row * EMB;
    float s = 0.f, sq = 0.f;
    for (int i = threadIdx.x; i < EMB; i += 256) { float v = xr[i]; s += v; sq += v * v; }
    #pragma unroll
    for (int o = 16; o; o >>= 1) {
        s  += __shfl_xor_sync(~0u, s,  o);
        sq += __shfl_xor_sync(~0u, sq, o);
    }
    __shared__ float red[16];
    __shared__ float s_mu, s_rstd;
    int wid = threadIdx.x >> 5, lid = threadIdx.x & 31;
    if (lid == 0) { red[wid] = s; red[8 + wid] = sq; }
    __syncthreads();
    if (threadIdx.x == 0) {
        float S = 0.f, SQ = 0.f;
        for (int i = 0; i < 8; i++) { S += red[i]; SQ += red[8 + i]; }
        float mu = S * (1.f / EMB);
        float var = SQ * (1.f / EMB) - mu * mu;
        s_mu = mu; s_rstd = rsqrtf(var + 1e-5f);
    }
    __syncthreads();
    float mk = (t < g_len[b]) ? 1.f : 0.f;
    float mu = s_mu, rstd = s_rstd;
    for (int i = threadIdx.x; i < EMB; i += 256) {
        float v = ((xr[i] - mu) * rstd * w[i] + bia[i]) * mk;
        __nv_bfloat16 h, l; split_bf16(v, h, l);
        yh[(size_t)row * EMB + i] = h;
        yl[(size_t)row * EMB + i] = l;
    }
}

// ---------------- mma.sync GEMM, K-chunk 32, hi|lo interleaved rows ----------------
// C[M,N] = A @ B^T (split-bf16, fp32 acc). 128x128 tile, 8 warps (2x4).
// Stage = A-tile 16KB + B-tile 16KB (row = [hi 64B | lo 64B]); 3 stages = 96KB
// -> 2 CTAs/SM. __launch_bounds__(256,2) keeps regs <= 128.
#define GEMM_SMEM (3 * 32768)

__global__ void __launch_bounds__(256, 2) gemm_mma(
    const __nv_bfloat16* __restrict__ Ahi, const __nv_bfloat16* __restrict__ Alo,
    const __nv_bfloat16* __restrict__ Bhi, const __nv_bfloat16* __restrict__ Blo,
    const float* __restrict__ Res, const float* __restrict__ Bias,
    float* __restrict__ Cf, __nv_bfloat16* __restrict__ Chi, __nv_bfloat16* __restrict__ Clo,
    int K, int ldc, int doRelu, int doMask)
{
    extern __shared__ char smem[];
    uint32_t sb = smem_u32(smem);
    int tid = threadIdx.x;
    int lane = tid & 31, wid = tid >> 5;
    int wm = (wid >> 2) * 64;
    int wn = (wid & 3) * 32;
    int m0 = blockIdx.y * 128, n0 = blockIdx.x * 128;

    int nc = K >> 5;   // chunks of 32 columns

    // stage layout: [A-tile 16KB][B-tile 16KB]; row r = 128B: units 0-3 hi, 4-7 lo
    auto load_chunk = [&](uint32_t st, int kc) {
        #pragma unroll
        for (int i = 0; i < 8; i++) {
            int g = tid + i * 256;          // 0..2047
            int tile = g >> 10;             // 0 = A, 1 = B
            int rem = g & 1023;
            int r = rem >> 3, u = rem & 7;
            uint32_t sw = sw128(r * 128 + u * 16);
            int col = kc + (u & 3) * 8;
            const __nv_bfloat16* src;
            if (tile == 0)
                src = ((u < 4) ? Ahi : Alo) + (size_t)(m0 + r) * K + col;
            else
                src = ((u < 4) ? Bhi : Blo) + (size_t)(n0 + r) * K + col;
            cp_async16(st + tile * 16384 + sw, src);
        }
        CP_COMMIT();
    };

    int grp = lane >> 3, lrow = lane & 7;
    int a_r = lrow + ((grp & 1) ? 8 : 0);
    int a_c = grp >> 1;
    int b_r = lrow + ((grp >> 1) ? 8 : 0);
    int b_c = grp & 1;

    float d[4][4][4];
    #pragma unroll
    for (int i = 0; i < 4; i++)
        #pragma unroll
        for (int j = 0; j < 4; j++)
            #pragma unroll
            for (int q = 0; q < 4; q++) d[i][j][q] = 0.f;

    load_chunk(sb, 0);
    load_chunk(sb + 32768, 32);
    CP_WAIT1();
    __syncthreads();

    for (int c = 0; c < nc; c++) {
        uint32_t st = sb + (c % 3) * 32768;
        if (c + 2 < nc) load_chunk(sb + ((c + 2) % 3) * 32768, (c + 2) * 32);

        #pragma unroll
        for (int ks = 0; ks < 2; ks++) {
            uint32_t ah[4][4], al[4][4];
            #pragma unroll
            for (int mt = 0; mt < 4; mt++) {
                uint32_t rb = (wm + mt * 16 + a_r) * 128;
                ldsm4(ah[mt], st + sw128(rb + (2 * ks + a_c) * 16));
                ldsm4(al[mt], st + sw128(rb + (4 + 2 * ks + a_c) * 16));
            }
            #pragma unroll
            for (int np = 0; np < 2; np++) {
                uint32_t rb = (wn + np * 16 + b_r) * 128;
                uint32_t th[4], tl[4];
                ldsm4(th, st + 16384 + sw128(rb + (2 * ks + b_c) * 16));
                ldsm4(tl, st + 16384 + sw128(rb + (4 + 2 * ks + b_c) * 16));
                #pragma unroll
                for (int mt = 0; mt < 4; mt++) {
                    mma_bf16(d[mt][np * 2],     ah[mt], &th[0]);
                    mma_bf16(d[mt][np * 2],     ah[mt], &tl[0]);
                    mma_bf16(d[mt][np * 2],     al[mt], &th[0]);
                    mma_bf16(d[mt][np * 2 + 1], ah[mt], &th[2]);
                    mma_bf16(d[mt][np * 2 + 1], ah[mt], &tl[2]);
                    mma_bf16(d[mt][np * 2 + 1], al[mt], &th[2]);
                }
            }
        }
        if (c + 2 < nc) CP_WAIT1(); else CP_WAIT0();
        __syncthreads();
    }

    // ---- epilogue: stage f32 accum through smem (reuse stage memory, 67.5KB <= 96KB) ----
    float* eb = (float*)smem;    // [128][132]
    int fr = lane >> 2, fc = (lane & 3) * 2;
    #pragma unroll
    for (int mt = 0; mt < 4; mt++)
        #pragma unroll
        for (int nt = 0; nt < 4; nt++) {
            int rr = wm + mt * 16 + fr;
            int cc = wn + nt * 8 + fc;
            *(float2*)&eb[rr * 132 + cc]       = make_float2(d[mt][nt][0], d[mt][nt][1]);
            *(float2*)&eb[(rr + 8) * 132 + cc] = make_float2(d[mt][nt][2], d[mt][nt][3]);
        }
    __syncthreads();

    #pragma unroll
    for (int it = 0; it < 16; it++) {
        int idx = tid + it * 256;
        int rr = idx >> 5;
        int cc = (idx & 31) * 4;
        int m = m0 + rr, n = n0 + cc;
        float4 v = *(float4*)&eb[rr * 132 + cc];
        if (Bias) {
            v.x += Bias[n]; v.y += Bias[n + 1]; v.z += Bias[n + 2]; v.w += Bias[n + 3];
        }
        if (Res) {
            float4 rv = *(const float4*)&Res[(size_t)m * ldc + n];
            v.x += rv.x; v.y += rv.y; v.z += rv.z; v.w += rv.w;
        }
        if (doRelu) {
            v.x = fmaxf(v.x, 0.f); v.y = fmaxf(v.y, 0.f);
            v.z = fmaxf(v.z, 0.f); v.w = fmaxf(v.w, 0.f);
        }
        if (doMask) {
            int bb = m >> 11, t = m & (SEQ - 1);
            float mk = (t < g_len[bb]) ? 1.f : 0.f;
            v.x *= mk; v.y *= mk; v.z *= mk; v.w *= mk;
        }
        if (Chi) {
            __nv_bfloat16 h[4], l[4];
            split_bf16(v.x, h[0], l[0]); split_bf16(v.y, h[1], l[1]);
            split_bf16(v.z, h[2], l[2]); split_bf16(v.w, h[3], l[3]);
            *(uint2*)&Chi[(size_t)m * ldc + n] = *(uint2*)h;
            *(uint2*)&Clo[(size_t)m * ldc + n] = *(uint2*)l;
        } else {
            *(float4*)&Cf[(size_t)m * ldc + n] = v;
        }
    }
}

// ---------------- Flash attention with split-bf16 mma.sync ----------------
// 64q x 64k tiles, 4 warps (16 q-rows each), softmax in registers.
#define ATTN_SMEM (6 * 8192)

__global__ void __launch_bounds__(128) attn_mma_kernel(
    const __nv_bfloat16* __restrict__ QKVh, const __nv_bfloat16* __restrict__ QKVl,
    __nv_bfloat16* __restrict__ Oh, __nv_bfloat16* __restrict__ Ol)
{
    extern __shared__ char smem[];
    uint32_t sb = smem_u32(smem);
    const uint32_t sQh = sb, sQl = sb + 8192, sKh = sb + 16384, sKl = sb + 24576,
                   sVh = sb + 32768, sVl = sb + 40960;
    int tid = threadIdx.x, lane = tid & 31, wid = tid >> 5;
    int b = blockIdx.z, h = blockIdx.y, qt = blockIdx.x;
    int q0 = qt * 64;
    int len = g_len[b];
    size_t rowbase = (size_t)b * SEQ;
    int cq = h * HS, ck = EMB + h * HS, cv = 2 * EMB + h * HS;

    // load Q tile (hi/lo), SW128
    #pragma unroll
    for (int i = 0; i < 4; i++) {
        int idx = tid + i * 128;
        int r = idx >> 3, c16 = idx & 7;
        uint32_t sw = sw128(r * 128 + c16 * 16);
        size_t g = (rowbase + q0 + r) * QKVW + cq + c16 * 8;
        cp_async16(sQh + sw, QKVh + g);
        cp_async16(sQl + sw, QKVl + g);
    }
    CP_COMMIT();

    float Oacc[8][4];
    #pragma unroll
    for (int j = 0; j < 8; j++)
        #pragma unroll
        for (int q = 0; q < 4; q++) Oacc[j][q] = 0.f;
    float mrow0 = -1e30f, mrow1 = -1e30f, lrow0 = 0.f, lrow1 = 0.f;

    const float scale = 0.03125f;  // 1024^-0.5
    int lenTiles = (len + 63) >> 6;
    int nT = min(qt + 1, lenTiles);

    int l15 = lane & 15, lh = lane >> 4;
    int grp = lane >> 3, lrow = lane & 7;
    int b_r = lrow + ((grp >> 1) ? 8 : 0);   // B-operand lane addressing (as in gemm)
    int b_c = grp & 1;
    int wq = wid * 16;
    int r0 = q0 + wq + (lane >> 2);   // global seq row of d0,d1 (row+8 for d2,d3)
    int dlo = (lane & 3) * 2;

    for (int kt = 0; kt < nT; kt++) {
        int s0 = kt * 64;
        __syncthreads();   // all warps done reading previous K/V
        #pragma unroll
        for (int i = 0; i < 4; i++) {
            int idx = tid + i * 128;
            int r = idx >> 3, c16 = idx & 7;
            uint32_t sw = sw128(r * 128 + c16 * 16);
            size_t gk = (rowbase + s0 + r) * QKVW + ck + c16 * 8;
            size_t gv = (rowbase + s0 + r) * QKVW + cv + c16 * 8;
            cp_async16(sKh + sw, QKVh + gk);
            cp_async16(sKl + sw, QKVl + gk);
            cp_async16(sVh + sw, QKVh + gv);
            cp_async16(sVl + sw, QKVl + gv);
        }
        CP_COMMIT();
        CP_WAIT0();
        __syncthreads();

        // ---- S = Q K^T (3-term split), fp32 frags ----
        float sacc[8][4];
        #pragma unroll
        for (int j = 0; j < 8; j++)
            #pragma unroll
            for (int q = 0; q < 4; q++) sacc[j][q] = 0.f;

        #pragma unroll
        for (int ks = 0; ks < 4; ks++) {
            uint32_t qh[4], ql[4];
            uint32_t aoff = sw128((wq + l15) * 128 + (ks * 2 + lh) * 16);
            ldsm4(qh, sQh + aoff);
            ldsm4(ql, sQl + aoff);
            #pragma unroll
            for (int np = 0; np < 4; np++) {
                uint32_t boff = sw128((np * 16 + b_r) * 128 + (ks * 2 + b_c) * 16);
                uint32_t kh[4], kl[4];
                ldsm4(kh, sKh + boff);
                ldsm4(kl, sKl + boff);
                mma_bf16(sacc[np * 2],     qh, &kh[0]);
                mma_bf16(sacc[np * 2],     qh, &kl[0]);
                mma_bf16(sacc[np * 2],     ql, &kh[0]);
                mma_bf16(sacc[np * 2 + 1], qh, &kh[2]);
                mma_bf16(sacc[np * 2 + 1], qh, &kl[2]);
                mma_bf16(sacc[np * 2 + 1], ql, &kh[2]);
            }
        }

        // ---- scale + mask + row max ----
        float rmax0 = -1e30f, rmax1 = -1e30f;
        #pragma unroll
        for (int j = 0; j < 8; j++) {
            int kj = s0 + j * 8 + dlo;
            #pragma unroll
            for (int q = 0; q < 4; q++) {
                int col = kj + (q & 1);
                int row = r0 + (q >> 1) * 8;
                float v = sacc[j][q] * scale;
                if (col > row || col >= len) v = -1e30f;
                sacc[j][q] = v;
            }
            rmax0 = fmaxf(rmax0, fmaxf(sacc[j][0], sacc[j][1]));
            rmax1 = fmaxf(rmax1, fmaxf(sacc[j][2], sacc[j][3]));
        }
        rmax0 = fmaxf(rmax0, __shfl_xor_sync(~0u, rmax0, 1));
        rmax0 = fmaxf(rmax0, __shfl_xor_sync(~0u, rmax0, 2));
        rmax1 = fmaxf(rmax1, __shfl_xor_sync(~0u, rmax1, 1));
        rmax1 = fmaxf(rmax1, __shfl_xor_sync(~0u, rmax1, 2));

        float mnew0 = fmaxf(mrow0, rmax0), mnew1 = fmaxf(mrow1, rmax1);
        float corr0 = __expf(mrow0 - mnew0), corr1 = __expf(mrow1 - mnew1);
        mrow0 = mnew0; mrow1 = mnew1;

        // ---- P = exp(S - m), row sums ----
        float rsum0 = 0.f, rsum1 = 0.f;
        #pragma unroll
        for (int j = 0; j < 8; j++) {
            sacc[j][0] = __expf(sacc[j][0] - mnew0);
            sacc[j][1] = __expf(sacc[j][1] - mnew0);
            sacc[j][2] = __expf(sacc[j][2] - mnew1);
            sacc[j][3] = __expf(sacc[j][3] - mnew1);
            rsum0 += sacc[j][0] + sacc[j][1];
            rsum1 += sacc[j][2] + sacc[j][3];
        }
        rsum0 += __shfl_xor_sync(~0u, rsum0, 1);
        rsum0 += __shfl_xor_sync(~0u, rsum0, 2);
        rsum1 += __shfl_xor_sync(~0u, rsum1, 1);
        rsum1 += __shfl_xor_sync(~0u, rsum1, 2);
        lrow0 = lrow0 * corr0 + rsum0;
        lrow1 = lrow1 * corr1 + rsum1;

        // ---- rescale O ----
        #pragma unroll
        for (int j = 0; j < 8; j++) {
            Oacc[j][0] *= corr0; Oacc[j][1] *= corr0;
            Oacc[j][2] *= corr1; Oacc[j][3] *= corr1;
        }

        // ---- O += P @ V (3-term split), V via ldmatrix.trans ----
        #pragma unroll
        for (int ks = 0; ks < 4; ks++) {
            int j0 = 2 * ks, j1 = j0 + 1;
            uint32_t ph[4], pl[4];
            split2(sacc[j0][0], sacc[j0][1], ph[0], pl[0]);
            split2(sacc[j0][2], sacc[j0][3], ph[1], pl[1]);
            split2(sacc[j1][0], sacc[j1][1], ph[2], pl[2]);
            split2(sacc[j1][2], sacc[j1][3], ph[3], pl[3]);
            #pragma unroll
            for (int dg = 0; dg < 4; dg++) {
                uint32_t voff = sw128((ks * 16 + l15) * 128 + (dg * 2 + lh) * 16);
                uint32_t vh[4], vl[4];
                ldsm4t(vh, sVh + voff);
                ldsm4t(vl, sVl + voff);
                mma_bf16(Oacc[dg * 2],     ph, &vh[0]);
                mma_bf16(Oacc[dg * 2],     ph, &vl[0]);
                mma_bf16(Oacc[dg * 2],     pl, &vh[0]);
                mma_bf16(Oacc[dg * 2 + 1], ph, &vh[2]);
                mma_bf16(Oacc[dg * 2 + 1], ph, &vl[2]);
                mma_bf16(Oacc[dg * 2 + 1], pl, &vh[2]);
            }
        }
    }

    // ---- final: O /= l, write bf16 hi/lo ----
    float inv0 = 1.f / lrow0, inv1 = 1.f / lrow1;
    size_t row0 = rowbase + r0, row1 = row0 + 8;
    #pragma unroll
    for (int j = 0; j < 8; j++) {
        int dc = h * HS + j * 8 + dlo;
        uint32_t uh, ul;
        split2(Oacc[j][0] * inv0, Oacc[j][1] * inv0, uh, ul);
        *(uint32_t*)&Oh[row0 * EMB + dc] = uh;
        *(uint32_t*)&Ol[row0 * EMB + dc] = ul;
        split2(Oacc[j][2] * inv1, Oacc[j][3] * inv1, uh, ul);
        *(uint32_t*)&Oh[row1 * EMB + dc] = uh;
        *(uint32_t*)&Ol[row1 * EMB + dc] = ul;
    }
}

// ---------------- launch ----------------
extern "C" void kernel_launch(void* const* d_in, const int* in_sizes, int n_in,
                              void* d_out, int out_size)
{
    const float* x      = (const float*)d_in[0];
    const unsigned char* mask = (const unsigned char*)d_in[1];
    const float* wq     = (const float*)d_in[2];
    const float* wk     = (const float*)d_in[3];
    const float* wv     = (const float*)d_in[4];
    const float* proj_w = (const float*)d_in[5];
    const float* proj_b = (const float*)d_in[6];
    const float* ff_w1  = (const float*)d_in[7];
    const float* ff_b1  = (const float*)d_in[8];
    const float* ff_w2  = (const float*)d_in[9];
    const float* ff_b2  = (const float*)d_in[10];
    const float* ln1w   = (const float*)d_in[11];
    const float* ln1b   = (const float*)d_in[12];
    const float* ln2w   = (const float*)d_in[13];
    const float* ln2b   = (const float*)d_in[14];
    float* out = (float*)d_out;

    __nv_bfloat16 *ahi, *alo, *ffh, *ffl, *qkvh, *qkvl;
    __nv_bfloat16 *wqkvh, *wqkvl, *wprojh, *wprojl, *wff1h, *wff1l, *wff2h, *wff2l;
    float *x1;
    cudaGetSymbolAddress((void**)&ahi, g_ahi);   cudaGetSymbolAddress((void**)&alo, g_alo);
    cudaGetSymbolAddress((void**)&ffh, g_ffhi);  cudaGetSymbolAddress((void**)&ffl, g_fflo);
    cudaGetSymbolAddress((void**)&qkvh, g_qkvh); cudaGetSymbolAddress((void**)&qkvl, g_qkvl);
    cudaGetSymbolAddress((void**)&wqkvh, g_wqkvh); cudaGetSymbolAddress((void**)&wqkvl, g_wqkvl);
    cudaGetSymbolAddress((void**)&wprojh, g_wprojh); cudaGetSymbolAddress((void**)&wprojl, g_wprojl);
    cudaGetSymbolAddress((void**)&wff1h, g_wff1h); cudaGetSymbolAddress((void**)&wff1l, g_wff1l);
    cudaGetSymbolAddress((void**)&wff2h, g_wff2h); cudaGetSymbolAddress((void**)&wff2l, g_wff2l);
    cudaGetSymbolAddress((void**)&x1, g_x1);

    cudaFuncSetAttribute(gemm_mma, cudaFuncAttributeMaxDynamicSharedMemorySize, GEMM_SMEM);
    cudaFuncSetAttribute(attn_mma_kernel, cudaFuncAttributeMaxDynamicSharedMemorySize, ATTN_SMEM);

    lengths_kernel<<<1, 256>>>(mask);

    // weight prep: transpose + hi/lo split
    wsplit_kernel<<<dim3(EMB/32, EMB/32), 256>>>(wq, wqkvh, wqkvl, EMB, EMB, 0,      EMB);
    wsplit_kernel<<<dim3(EMB/32, EMB/32), 256>>>(wk, wqkvh, wqkvl, EMB, EMB, EMB,    EMB);
    wsplit_kernel<<<dim3(EMB/32, EMB/32), 256>>>(wv, wqkvh, wqkvl, EMB, EMB, 2*EMB,  EMB);
    wsplit_kernel<<<dim3(EMB/32, EMB/32), 256>>>(proj_w, wprojh, wprojl, EMB, EMB, 0, EMB);
    wsplit_kernel<<<dim3(DFF/32, EMB/32), 256>>>(ff_w1, wff1h, wff1l, EMB, DFF, 0,   EMB);
    wsplit_kernel<<<dim3(EMB/32, DFF/32), 256>>>(ff_w2, wff2h, wff2l, DFF, EMB, 0,   DFF);

    // h = LN1(x)*m (split)
    ln_split_kernel<<<MROWS, 256>>>(x, ln1w, ln1b, ahi, alo);

    // qkv = h @ Wqkv^T -> bf16 hi/lo  [8192 x 3072]
    gemm_mma<<<dim3(QKVW/128, MROWS/128), 256, GEMM_SMEM>>>(
        ahi, alo, wqkvh, wqkvl, nullptr, nullptr, nullptr, qkvh, qkvl,
        EMB, QKVW, 0, 0);

    // attention (tensor-core flash) -> ahi/alo
    attn_mma_kernel<<<dim3(SEQ/64, NH, BATCH), 128, ATTN_SMEM>>>(qkvh, qkvl, ahi, alo);

    // x1 = x + attn @ proj_w + proj_b
    gemm_mma<<<dim3(EMB/128, MROWS/128), 256, GEMM_SMEM>>>(
        ahi, alo, wprojh, wprojl, x, proj_b, x1, nullptr, nullptr,
        EMB, EMB, 0, 0);

    // h2 = LN2(x1)*m (split)
    ln_split_kernel<<<MROWS, 256>>>(x1, ln2w, ln2b, ahi, alo);

    // ff = relu(h2 @ ff_w1 + b1) -> bf16 hi/lo
    gemm_mma<<<dim3(DFF/128, MROWS/128), 256, GEMM_SMEM>>>(
        ahi, alo, wff1h, wff1l, nullptr, ff_b1, nullptr, ffh, ffl,
        EMB, DFF, 1, 0);

    // out = (x1 + ff @ ff_w2 + b2) * m
    gemm_mma<<<dim3(EMB/128, MROWS/128), 256, GEMM_SMEM>>>(
        ffh, ffl, wff2h, wff2l, x1, ff_b2, out, nullptr, nullptr,
        DFF, EMB, 0, 1);
}